// round 5
// baseline (speedup 1.0000x reference)
#include <cuda_runtime.h>
#include <cuda_bf16.h>
#include <cstdint>

#define BSZ  8
#define LSZ  2048
#define DMSZ 1024
#define DHSZ 1024
#define MSZ  (BSZ * LSZ)   // 16384

// ---------------- scratch (__device__ globals; allocation-free rule) -------
__device__ __nv_bfloat16 g_xhi[(size_t)MSZ * DMSZ];
__device__ __nv_bfloat16 g_xlo[(size_t)MSZ * DMSZ];
__device__ __nv_bfloat16 g_dwhi[DHSZ * DMSZ], g_dwlo[DHSZ * DMSZ];
__device__ __nv_bfloat16 g_Bwhi[DHSZ * DMSZ], g_Bwlo[DHSZ * DMSZ];
__device__ __nv_bfloat16 g_Cwhi[DMSZ * DHSZ], g_Cwlo[DMSZ * DHSZ];
__device__ __nv_bfloat16 g_Dwhi[DMSZ * DMSZ], g_Dwlo[DMSZ * DMSZ];
__device__ float g_Abar[(size_t)MSZ * DHSZ];
__device__ float g_Bbar[(size_t)MSZ * DHSZ];
__device__ __nv_bfloat16 g_Hhi[(size_t)MSZ * DHSZ];
__device__ __nv_bfloat16 g_Hlo[(size_t)MSZ * DHSZ];

// ---------------- helpers --------------------------------------------------
__device__ __forceinline__ uint32_t smem_u32(const void* p) {
    uint32_t a;
    asm("{ .reg .u64 t; cvta.to.shared.u64 t, %1; cvt.u32.u64 %0, t; }"
        : "=r"(a) : "l"(p));
    return a;
}

// SMEM tile layout: rows of 32 bf16 = 64B = 4 chunks of 16B.
// chunk' = chunk ^ ((row>>1)&3)  -> conflict-free for ldmatrix + stores.
__device__ __forceinline__ uint32_t sw_chunk_off(int r, int c) {
    return (uint32_t)(((r << 2) | (c ^ ((r >> 1) & 3))) << 4);
}

__device__ __forceinline__ void ldsm4(uint32_t* d, uint32_t addr) {
    asm volatile("ldmatrix.sync.aligned.m8n8.x4.shared.b16 {%0,%1,%2,%3}, [%4];"
                 : "=r"(d[0]), "=r"(d[1]), "=r"(d[2]), "=r"(d[3]) : "r"(addr));
}

__device__ __forceinline__ void mma16816(float* c, const uint32_t* a, const uint32_t* b) {
    asm volatile(
        "mma.sync.aligned.m16n8k16.row.col.f32.bf16.bf16.f32 "
        "{%0,%1,%2,%3}, {%4,%5,%6,%7}, {%8,%9}, {%0,%1,%2,%3};"
        : "+f"(c[0]), "+f"(c[1]), "+f"(c[2]), "+f"(c[3])
        : "r"(a[0]), "r"(a[1]), "r"(a[2]), "r"(a[3]), "r"(b[0]), "r"(b[1]));
}

__device__ __forceinline__ uint32_t addrA(uint32_t sbase, int mrow, int c0) {
    int l = threadIdx.x & 31;
    int r = mrow + (l & 15);
    int c = c0 + (l >> 4);
    return sbase + sw_chunk_off(r, c);
}
__device__ __forceinline__ uint32_t addrB(uint32_t sbase, int nrow, int c0) {
    int l = threadIdx.x & 31;
    int r = nrow + (l & 7) + ((l >> 4) << 3);
    int c = c0 + ((l >> 3) & 1);
    return sbase + sw_chunk_off(r, c);
}

template <int ROWS>
__device__ __forceinline__ void load_tile_async(uint32_t sbase,
                                                const __nv_bfloat16* __restrict__ g,
                                                int row0, int kb)
{
    int t = threadIdx.x;
#pragma unroll
    for (int i = 0; i < (ROWS * 4) / 256; i++) {
        int idx = i * 256 + t;
        int r = idx >> 2;
        int c = idx & 3;
        const char* src = (const char*)(g + (size_t)(row0 + r) * 1024 + kb) + c * 16;
        uint32_t dst = sbase + sw_chunk_off(r, c);
        asm volatile("cp.async.cg.shared.global [%0], [%1], 16;"
                     :: "r"(dst), "l"(src) : "memory");
    }
}
#define CP_COMMIT()  asm volatile("cp.async.commit_group;" ::: "memory")
#define CP_WAIT(n)   asm volatile("cp.async.wait_group %0;" :: "n"(n) : "memory")

// ---------------- prep: fp32 -> bf16 hi/lo split ---------------------------
__global__ __launch_bounds__(256) void convert_kernel(
    const float* __restrict__ src, __nv_bfloat16* __restrict__ hi,
    __nv_bfloat16* __restrict__ lo, int n4)
{
    int i = blockIdx.x * 256 + threadIdx.x;
    if (i >= n4) return;
    float4 v = ((const float4*)src)[i];
    __nv_bfloat16 h0 = __float2bfloat16_rn(v.x);
    __nv_bfloat16 h1 = __float2bfloat16_rn(v.y);
    __nv_bfloat16 h2 = __float2bfloat16_rn(v.z);
    __nv_bfloat16 h3 = __float2bfloat16_rn(v.w);
    __nv_bfloat16 l0 = __float2bfloat16_rn(v.x - __bfloat162float(h0));
    __nv_bfloat16 l1 = __float2bfloat16_rn(v.y - __bfloat162float(h1));
    __nv_bfloat16 l2 = __float2bfloat16_rn(v.z - __bfloat162float(h2));
    __nv_bfloat16 l3 = __float2bfloat16_rn(v.w - __bfloat162float(h3));
    __nv_bfloat162* h2p = (__nv_bfloat162*)(hi + (size_t)i * 4);
    __nv_bfloat162* l2p = (__nv_bfloat162*)(lo + (size_t)i * 4);
    h2p[0] = __halves2bfloat162(h0, h1);
    h2p[1] = __halves2bfloat162(h2, h3);
    l2p[0] = __halves2bfloat162(l0, l1);
    l2p[1] = __halves2bfloat162(l2, l3);
}

// ---------------- kernel 1: dual GEMM (x@dw^T, x@Bw^T) + SSM epilogue ------
// CTA 128(M) x 64(N); 8 warps 4m x 2n; warp tile 32x32; BK=32; 3-stage pipe.
// Stage (32KB): Ah 0, Al 8192, W1h 16384, W1l 20480, W2h 24576, W2l 28672.
__global__ __launch_bounds__(256, 1)
void gemm1_kernel(const float* __restrict__ dbias, const float* __restrict__ Bb,
                  const float* __restrict__ Avec)
{
    extern __shared__ char smem[];
    uint32_t sb = smem_u32(smem);
    const int t = threadIdx.x, wid = t >> 5, lane = t & 31;
    const int m0 = blockIdx.y * 128, n0 = blockIdx.x * 64;
    const int wm = (wid & 3) * 32;
    const int wn = (wid >> 2) * 32;

    float acc1[2][4][4], acc2[2][4][4];
#pragma unroll
    for (int i = 0; i < 2; i++)
#pragma unroll
        for (int j = 0; j < 4; j++)
#pragma unroll
            for (int q = 0; q < 4; q++) { acc1[i][j][q] = 0.f; acc2[i][j][q] = 0.f; }

    auto issue_stage = [&](int s, int kidx) {
        uint32_t st = sb + s * 32768;
        int kb = kidx * 32;
        load_tile_async<128>(st,          g_xhi,  m0, kb);
        load_tile_async<128>(st + 8192,   g_xlo,  m0, kb);
        load_tile_async<64> (st + 16384,  g_dwhi, n0, kb);
        load_tile_async<64> (st + 20480,  g_dwlo, n0, kb);
        load_tile_async<64> (st + 24576,  g_Bwhi, n0, kb);
        load_tile_async<64> (st + 28672,  g_Bwlo, n0, kb);
        CP_COMMIT();
    };
    issue_stage(0, 0);
    issue_stage(1, 1);

    const int K = 32;
    for (int k = 0; k < K; k++) {
        if (k + 2 < K) CP_WAIT(1); else CP_WAIT(0);
        __syncthreads();
        if (k + 2 < K) issue_stage((k + 2) % 3, k + 2);

        uint32_t st = sb + (k % 3) * 32768;
#pragma unroll
        for (int kk = 0; kk < 2; kk++) {
            int c0 = kk * 2;
            uint32_t ah[2][4], al[2][4];
#pragma unroll
            for (int mt = 0; mt < 2; mt++) {
                ldsm4(ah[mt], addrA(st,        wm + mt * 16, c0));
                ldsm4(al[mt], addrA(st + 8192, wm + mt * 16, c0));
            }
            uint32_t b1h[8], b1l[8], b2h[8], b2l[8];
            ldsm4(b1h,     addrB(st + 16384, wn,      c0));
            ldsm4(b1h + 4, addrB(st + 16384, wn + 16, c0));
            ldsm4(b1l,     addrB(st + 20480, wn,      c0));
            ldsm4(b1l + 4, addrB(st + 20480, wn + 16, c0));
            ldsm4(b2h,     addrB(st + 24576, wn,      c0));
            ldsm4(b2h + 4, addrB(st + 24576, wn + 16, c0));
            ldsm4(b2l,     addrB(st + 28672, wn,      c0));
            ldsm4(b2l + 4, addrB(st + 28672, wn + 16, c0));
            // term-major: accumulator reuse distance = 16 MMAs
#pragma unroll
            for (int mt = 0; mt < 2; mt++)
#pragma unroll
                for (int nt = 0; nt < 4; nt++) {
                    mma16816(acc1[mt][nt], ah[mt], &b1h[nt * 2]);
                    mma16816(acc2[mt][nt], ah[mt], &b2h[nt * 2]);
                }
#pragma unroll
            for (int mt = 0; mt < 2; mt++)
#pragma unroll
                for (int nt = 0; nt < 4; nt++) {
                    mma16816(acc1[mt][nt], ah[mt], &b1l[nt * 2]);
                    mma16816(acc2[mt][nt], ah[mt], &b2l[nt * 2]);
                }
#pragma unroll
            for (int mt = 0; mt < 2; mt++)
#pragma unroll
                for (int nt = 0; nt < 4; nt++) {
                    mma16816(acc1[mt][nt], al[mt], &b1h[nt * 2]);
                    mma16816(acc2[mt][nt], al[mt], &b2h[nt * 2]);
                }
        }
    }

    // epilogue
    const int lr = lane >> 2, lc = lane & 3;
    float dbv[4][2], avv[4][2], bbv[4][2];
#pragma unroll
    for (int nt = 0; nt < 4; nt++)
#pragma unroll
        for (int j = 0; j < 2; j++) {
            int n = n0 + wn + nt * 8 + lc * 2 + j;
            dbv[nt][j] = __ldg(&dbias[n]);
            avv[nt][j] = __ldg(&Avec[n]);
            bbv[nt][j] = __ldg(&Bb[n]);
        }
#pragma unroll
    for (int mt = 0; mt < 2; mt++)
#pragma unroll
        for (int half = 0; half < 2; half++) {
            int m = m0 + wm + mt * 16 + half * 8 + lr;
            size_t rowo = (size_t)m * DHSZ;
#pragma unroll
            for (int nt = 0; nt < 4; nt++) {
                int n = n0 + wn + nt * 8 + lc * 2;
                float2 oa, ob;
#pragma unroll
                for (int j = 0; j < 2; j++) {
                    float t1 = acc1[mt][nt][half * 2 + j] + dbv[nt][j];
                    float e = __expf(-fabsf(t1));
                    float delta = fmaxf(t1, 0.f) + __logf(1.f + e);
                    float a = __expf(delta * avv[nt][j]);
                    float b = delta * (acc2[mt][nt][half * 2 + j] + bbv[nt][j]);
                    if (j == 0) { oa.x = a; ob.x = b; } else { oa.y = a; ob.y = b; }
                }
                *(float2*)&g_Abar[rowo + n] = oa;
                *(float2*)&g_Bbar[rowo + n] = ob;
            }
        }
}

// ---------------- kernel 2: linear recurrence scan -------------------------
__global__ __launch_bounds__(256) void scan_kernel()
{
    int c = blockIdx.x * 256 + threadIdx.x;   // 0..8191
    int b = c >> 10;
    int h = c & (DHSZ - 1);
    size_t base = (size_t)b * LSZ * DHSZ + h;

    float hp = 0.f;
    for (int l0 = 0; l0 < LSZ; l0 += 16) {
        float av[16], bv[16];
#pragma unroll
        for (int u = 0; u < 16; u++) {
            size_t o = base + (size_t)(l0 + u) * DHSZ;
            av[u] = g_Abar[o];
            bv[u] = g_Bbar[o];
        }
#pragma unroll
        for (int u = 0; u < 16; u++) {
            hp = fmaf(av[u], hp, bv[u]);
            size_t o = base + (size_t)(l0 + u) * DHSZ;
            __nv_bfloat16 hh = __float2bfloat16_rn(hp);
            g_Hhi[o] = hh;
            g_Hlo[o] = __float2bfloat16_rn(hp - __bfloat162float(hh));
        }
    }
}

// ---------------- kernel 3: out = h@Cw^T + x@Dw^T + Cb + Db ----------------
// CTA 128x128; 8 warps 2m x 4n; warp tile 64x32; BK=32; 3-stage pipe.
// Stage (32KB): Ah 0, Al 8192, Wh 16384, Wl 24576.
__global__ __launch_bounds__(256, 1)
void gemm3_kernel(const float* __restrict__ Cb, const float* __restrict__ Db,
                  float* __restrict__ out)
{
    extern __shared__ char smem[];
    uint32_t sb = smem_u32(smem);
    const int t = threadIdx.x, wid = t >> 5, lane = t & 31;
    const int m0 = blockIdx.y * 128, n0 = blockIdx.x * 128;
    const int wm = (wid & 1) * 64;
    const int wn = (wid >> 1) * 32;

    float acc[4][4][4];
#pragma unroll
    for (int i = 0; i < 4; i++)
#pragma unroll
        for (int j = 0; j < 4; j++)
#pragma unroll
            for (int q = 0; q < 4; q++) acc[i][j][q] = 0.f;

    auto issue_stage = [&](int s, int kidx) {
        const __nv_bfloat16 *Ah, *Al, *Wh, *Wl;
        if (kidx < 32) { Ah = g_Hhi; Al = g_Hlo; Wh = g_Cwhi; Wl = g_Cwlo; }
        else           { Ah = g_xhi; Al = g_xlo; Wh = g_Dwhi; Wl = g_Dwlo; }
        int kb = (kidx & 31) * 32;
        uint32_t st = sb + s * 32768;
        load_tile_async<128>(st,          Ah, m0, kb);
        load_tile_async<128>(st + 8192,   Al, m0, kb);
        load_tile_async<128>(st + 16384,  Wh, n0, kb);
        load_tile_async<128>(st + 24576,  Wl, n0, kb);
        CP_COMMIT();
    };
    issue_stage(0, 0);
    issue_stage(1, 1);

    const int K = 64;
    for (int k = 0; k < K; k++) {
        if (k + 2 < K) CP_WAIT(1); else CP_WAIT(0);
        __syncthreads();
        if (k + 2 < K) issue_stage((k + 2) % 3, k + 2);

        uint32_t st = sb + (k % 3) * 32768;
#pragma unroll
        for (int kk = 0; kk < 2; kk++) {
            int c0 = kk * 2;
            uint32_t ah[4][4], al[4][4];
#pragma unroll
            for (int mt = 0; mt < 4; mt++) {
                ldsm4(ah[mt], addrA(st,        wm + mt * 16, c0));
                ldsm4(al[mt], addrA(st + 8192, wm + mt * 16, c0));
            }
            uint32_t bh[8], bl[8];
            ldsm4(bh,     addrB(st + 16384, wn,      c0));
            ldsm4(bh + 4, addrB(st + 16384, wn + 16, c0));
            ldsm4(bl,     addrB(st + 24576, wn,      c0));
            ldsm4(bl + 4, addrB(st + 24576, wn + 16, c0));
            // term-major ordering: reuse distance = 16
#pragma unroll
            for (int mt = 0; mt < 4; mt++)
#pragma unroll
                for (int nt = 0; nt < 4; nt++)
                    mma16816(acc[mt][nt], ah[mt], &bh[nt * 2]);
#pragma unroll
            for (int mt = 0; mt < 4; mt++)
#pragma unroll
                for (int nt = 0; nt < 4; nt++)
                    mma16816(acc[mt][nt], ah[mt], &bl[nt * 2]);
#pragma unroll
            for (int mt = 0; mt < 4; mt++)
#pragma unroll
                for (int nt = 0; nt < 4; nt++)
                    mma16816(acc[mt][nt], al[mt], &bh[nt * 2]);
        }
    }

    const int lr = lane >> 2, lc = lane & 3;
    float biasv[4][2];
#pragma unroll
    for (int nt = 0; nt < 4; nt++)
#pragma unroll
        for (int j = 0; j < 2; j++) {
            int n = n0 + wn + nt * 8 + lc * 2 + j;
            biasv[nt][j] = __ldg(&Cb[n]) + __ldg(&Db[n]);
        }
#pragma unroll
    for (int mt = 0; mt < 4; mt++)
#pragma unroll
        for (int half = 0; half < 2; half++) {
            int m = m0 + wm + mt * 16 + half * 8 + lr;
            size_t rowo = (size_t)m * DMSZ;
#pragma unroll
            for (int nt = 0; nt < 4; nt++) {
                int n = n0 + wn + nt * 8 + lc * 2;
                float2 o;
                o.x = acc[mt][nt][half * 2 + 0] + biasv[nt][0];
                o.y = acc[mt][nt][half * 2 + 1] + biasv[nt][1];
                *(float2*)&out[rowo + n] = o;
            }
        }
}

// ---------------- launch ---------------------------------------------------
// Inputs: 0:x 1:A 2:Bw 3:Bb 4:Cw 5:Cb 6:Dw 7:Db 8:dw 9:db
extern "C" void kernel_launch(void* const* d_in, const int* in_sizes, int n_in,
                              void* d_out, int out_size)
{
    const float* x    = (const float*)d_in[0];
    const float* Avec = (const float*)d_in[1];
    const float* Bw   = (const float*)d_in[2];
    const float* Bb   = (const float*)d_in[3];
    const float* Cw   = (const float*)d_in[4];
    const float* Cb   = (const float*)d_in[5];
    const float* Dw   = (const float*)d_in[6];
    const float* Db   = (const float*)d_in[7];
    const float* dw   = (const float*)d_in[8];
    const float* db   = (const float*)d_in[9];
    float* out = (float*)d_out;

    void *xhi, *xlo, *dwhi, *dwlo, *bwhi, *bwlo, *cwhi, *cwlo, *Dwhi, *Dwlo;
    cudaGetSymbolAddress(&xhi, g_xhi);   cudaGetSymbolAddress(&xlo, g_xlo);
    cudaGetSymbolAddress(&dwhi, g_dwhi); cudaGetSymbolAddress(&dwlo, g_dwlo);
    cudaGetSymbolAddress(&bwhi, g_Bwhi); cudaGetSymbolAddress(&bwlo, g_Bwlo);
    cudaGetSymbolAddress(&cwhi, g_Cwhi); cudaGetSymbolAddress(&cwlo, g_Cwlo);
    cudaGetSymbolAddress(&Dwhi, g_Dwhi); cudaGetSymbolAddress(&Dwlo, g_Dwlo);

    cudaFuncSetAttribute(gemm1_kernel, cudaFuncAttributeMaxDynamicSharedMemorySize, 98304);
    cudaFuncSetAttribute(gemm3_kernel, cudaFuncAttributeMaxDynamicSharedMemorySize, 98304);

    int nx4 = (MSZ * DMSZ) / 4;
    int nw4 = (DHSZ * DMSZ) / 4;
    convert_kernel<<<nx4 / 256, 256>>>(x,  (__nv_bfloat16*)xhi,  (__nv_bfloat16*)xlo,  nx4);
    convert_kernel<<<nw4 / 256, 256>>>(dw, (__nv_bfloat16*)dwhi, (__nv_bfloat16*)dwlo, nw4);
    convert_kernel<<<nw4 / 256, 256>>>(Bw, (__nv_bfloat16*)bwhi, (__nv_bfloat16*)bwlo, nw4);
    convert_kernel<<<nw4 / 256, 256>>>(Cw, (__nv_bfloat16*)cwhi, (__nv_bfloat16*)cwlo, nw4);
    convert_kernel<<<nw4 / 256, 256>>>(Dw, (__nv_bfloat16*)Dwhi, (__nv_bfloat16*)Dwlo, nw4);

    dim3 g1(DHSZ / 64, MSZ / 128);    // (16, 128)
    gemm1_kernel<<<g1, 256, 98304>>>(db, Bb, Avec);

    scan_kernel<<<(BSZ * DHSZ) / 256, 256>>>();

    dim3 g3(DMSZ / 128, MSZ / 128);   // (8, 128)
    gemm3_kernel<<<g3, 256, 98304>>>(Cb, Db, out);
}

// round 10
// speedup vs baseline: 1.2052x; 1.2052x over previous
#include <cuda_runtime.h>
#include <cuda_fp16.h>
#include <cuda_bf16.h>
#include <cstdint>

#define BSZ  8
#define LSZ  2048
#define DMSZ 1024
#define DHSZ 1024
#define MSZ  (BSZ * LSZ)   // 16384

// ---------------- scratch (__device__ globals; allocation-free rule) -------
// fp16 side (range-safe tensors only: x, dw, Bw, Dw)
__device__ __half g_xhi[(size_t)MSZ * DMSZ];
__device__ __half g_xlo[(size_t)MSZ * DMSZ];
__device__ __half g_dwh[DHSZ * DMSZ];
__device__ __half g_Bwh[DHSZ * DMSZ];
__device__ __half g_Dwh[DMSZ * DMSZ];
// bf16 side (wide-range h path)
__device__ __nv_bfloat16 g_Cwhi[DMSZ * DHSZ], g_Cwlo[DMSZ * DHSZ];
__device__ __nv_bfloat16 g_Hhi[(size_t)MSZ * DHSZ];
__device__ __nv_bfloat16 g_Hlo[(size_t)MSZ * DHSZ];
// fp32 intermediates
__device__ float g_Abar[(size_t)MSZ * DHSZ];
__device__ float g_Bbar[(size_t)MSZ * DHSZ];

// ---------------- helpers --------------------------------------------------
__device__ __forceinline__ uint32_t smem_u32(const void* p) {
    uint32_t a;
    asm("{ .reg .u64 t; cvta.to.shared.u64 t, %1; cvt.u32.u64 %0, t; }"
        : "=r"(a) : "l"(p));
    return a;
}

// SMEM tile: rows of 32 16-bit elems = 64B = 4 chunks of 16B.
// chunk' = chunk ^ ((row>>1)&3) -> conflict-free for ldmatrix + stores.
__device__ __forceinline__ uint32_t sw_chunk_off(int r, int c) {
    return (uint32_t)(((r << 2) | (c ^ ((r >> 1) & 3))) << 4);
}

__device__ __forceinline__ void ldsm4(uint32_t* d, uint32_t addr) {
    asm volatile("ldmatrix.sync.aligned.m8n8.x4.shared.b16 {%0,%1,%2,%3}, [%4];"
                 : "=r"(d[0]), "=r"(d[1]), "=r"(d[2]), "=r"(d[3]) : "r"(addr));
}

__device__ __forceinline__ void mma_f16(float* c, const uint32_t* a, const uint32_t* b) {
    asm volatile(
        "mma.sync.aligned.m16n8k16.row.col.f32.f16.f16.f32 "
        "{%0,%1,%2,%3}, {%4,%5,%6,%7}, {%8,%9}, {%0,%1,%2,%3};"
        : "+f"(c[0]), "+f"(c[1]), "+f"(c[2]), "+f"(c[3])
        : "r"(a[0]), "r"(a[1]), "r"(a[2]), "r"(a[3]), "r"(b[0]), "r"(b[1]));
}
__device__ __forceinline__ void mma_bf16(float* c, const uint32_t* a, const uint32_t* b) {
    asm volatile(
        "mma.sync.aligned.m16n8k16.row.col.f32.bf16.bf16.f32 "
        "{%0,%1,%2,%3}, {%4,%5,%6,%7}, {%8,%9}, {%0,%1,%2,%3};"
        : "+f"(c[0]), "+f"(c[1]), "+f"(c[2]), "+f"(c[3])
        : "r"(a[0]), "r"(a[1]), "r"(a[2]), "r"(a[3]), "r"(b[0]), "r"(b[1]));
}

__device__ __forceinline__ uint32_t addrA(uint32_t sbase, int mrow, int c0) {
    int l = threadIdx.x & 31;
    int r = mrow + (l & 15);
    int c = c0 + (l >> 4);
    return sbase + sw_chunk_off(r, c);
}
__device__ __forceinline__ uint32_t addrB(uint32_t sbase, int nrow, int c0) {
    int l = threadIdx.x & 31;
    int r = nrow + (l & 7) + ((l >> 4) << 3);
    int c = c0 + ((l >> 3) & 1);
    return sbase + sw_chunk_off(r, c);
}

// Generic 16-bit tile loader (fp16 or bf16): ROWS x 32 elems at (row0, kb).
template <int ROWS>
__device__ __forceinline__ void load_tile_async(uint32_t sbase,
                                                const void* __restrict__ g,
                                                int row0, int kb)
{
    int t = threadIdx.x;
    const char* gb = (const char*)g + ((size_t)row0 * 1024 + kb) * 2;
#pragma unroll
    for (int i = 0; i < (ROWS * 4) / 256; i++) {
        int idx = i * 256 + t;
        int r = idx >> 2;
        int c = idx & 3;
        const char* src = gb + (size_t)r * 2048 + c * 16;
        uint32_t dst = sbase + sw_chunk_off(r, c);
        asm volatile("cp.async.cg.shared.global [%0], [%1], 16;"
                     :: "r"(dst), "l"(src) : "memory");
    }
}
#define CP_COMMIT()  asm volatile("cp.async.commit_group;" ::: "memory")
#define CP_WAIT(n)   asm volatile("cp.async.wait_group %0;" :: "n"(n) : "memory")

// ---------------- prep kernels ---------------------------------------------
__global__ __launch_bounds__(256) void convert_x_kernel(
    const float* __restrict__ src, __half* __restrict__ hi,
    __half* __restrict__ lo, int n4)
{
    int i = blockIdx.x * 256 + threadIdx.x;
    if (i >= n4) return;
    float4 v = ((const float4*)src)[i];
    __half h0 = __float2half_rn(v.x), h1 = __float2half_rn(v.y);
    __half h2 = __float2half_rn(v.z), h3 = __float2half_rn(v.w);
    __half l0 = __float2half_rn(v.x - __half2float(h0));
    __half l1 = __float2half_rn(v.y - __half2float(h1));
    __half l2 = __float2half_rn(v.z - __half2float(h2));
    __half l3 = __float2half_rn(v.w - __half2float(h3));
    __half2* hp = (__half2*)(hi + (size_t)i * 4);
    __half2* lp = (__half2*)(lo + (size_t)i * 4);
    hp[0] = __halves2half2(h0, h1);
    hp[1] = __halves2half2(h2, h3);
    lp[0] = __halves2half2(l0, l1);
    lp[1] = __halves2half2(l2, l3);
}

// dw, Bw, Dw -> single fp16 (blockIdx.y selects)
__global__ __launch_bounds__(256) void convert_w16_kernel(
    const float* __restrict__ s0, const float* __restrict__ s1,
    const float* __restrict__ s2,
    __half* __restrict__ d0, __half* __restrict__ d1, __half* __restrict__ d2)
{
    const float* s;
    __half* d;
    switch (blockIdx.y) {
        case 0:  s = s0; d = d0; break;
        case 1:  s = s1; d = d1; break;
        default: s = s2; d = d2; break;
    }
    int i = blockIdx.x * 256 + threadIdx.x;
    float4 v = ((const float4*)s)[i];
    __half2* dp = (__half2*)(d + (size_t)i * 4);
    dp[0] = __halves2half2(__float2half_rn(v.x), __float2half_rn(v.y));
    dp[1] = __halves2half2(__float2half_rn(v.z), __float2half_rn(v.w));
}

// Cw -> bf16 hi/lo
__global__ __launch_bounds__(256) void convert_cw_kernel(
    const float* __restrict__ src, __nv_bfloat16* __restrict__ hi,
    __nv_bfloat16* __restrict__ lo)
{
    int i = blockIdx.x * 256 + threadIdx.x;
    float4 v = ((const float4*)src)[i];
    __nv_bfloat16 h0 = __float2bfloat16_rn(v.x);
    __nv_bfloat16 h1 = __float2bfloat16_rn(v.y);
    __nv_bfloat16 h2 = __float2bfloat16_rn(v.z);
    __nv_bfloat16 h3 = __float2bfloat16_rn(v.w);
    __nv_bfloat16 l0 = __float2bfloat16_rn(v.x - __bfloat162float(h0));
    __nv_bfloat16 l1 = __float2bfloat16_rn(v.y - __bfloat162float(h1));
    __nv_bfloat16 l2 = __float2bfloat16_rn(v.z - __bfloat162float(h2));
    __nv_bfloat16 l3 = __float2bfloat16_rn(v.w - __bfloat162float(h3));
    __nv_bfloat162* hp = (__nv_bfloat162*)(hi + (size_t)i * 4);
    __nv_bfloat162* lp = (__nv_bfloat162*)(lo + (size_t)i * 4);
    hp[0] = __halves2bfloat162(h0, h1);
    hp[1] = __halves2bfloat162(h2, h3);
    lp[0] = __halves2bfloat162(l0, l1);
    lp[1] = __halves2bfloat162(l2, l3);
}

// ---------------- kernel 1: dual GEMM (x@dw^T, x@Bw^T) + SSM epilogue ------
// fp16 2-term. CTA 128x64; 8 warps 4m x 2n; warp 32x32; BK=32; 3-stage pipe.
// Stage (24KB): xh 0, xl 8192, dw 16384, Bw 20480.
__global__ __launch_bounds__(256, 1)
void gemm1_kernel(const float* __restrict__ dbias, const float* __restrict__ Bb,
                  const float* __restrict__ Avec)
{
    extern __shared__ char smem[];
    uint32_t sb = smem_u32(smem);
    const int t = threadIdx.x, wid = t >> 5, lane = t & 31;
    const int m0 = blockIdx.y * 128, n0 = blockIdx.x * 64;
    const int wm = (wid & 3) * 32;
    const int wn = (wid >> 2) * 32;

    float acc1[2][4][4], acc2[2][4][4];
#pragma unroll
    for (int i = 0; i < 2; i++)
#pragma unroll
        for (int j = 0; j < 4; j++)
#pragma unroll
            for (int q = 0; q < 4; q++) { acc1[i][j][q] = 0.f; acc2[i][j][q] = 0.f; }

    auto issue_stage = [&](int s, int kidx) {
        uint32_t st = sb + s * 24576;
        int kb = kidx * 32;
        load_tile_async<128>(st,          g_xhi, m0, kb);
        load_tile_async<128>(st + 8192,   g_xlo, m0, kb);
        load_tile_async<64> (st + 16384,  g_dwh, n0, kb);
        load_tile_async<64> (st + 20480,  g_Bwh, n0, kb);
        CP_COMMIT();
    };
    issue_stage(0, 0);
    issue_stage(1, 1);

    const int K = 32;
    for (int k = 0; k < K; k++) {
        if (k + 2 < K) CP_WAIT(1); else CP_WAIT(0);
        __syncthreads();
        if (k + 2 < K) issue_stage((k + 2) % 3, k + 2);

        uint32_t st = sb + (k % 3) * 24576;
#pragma unroll
        for (int kk = 0; kk < 2; kk++) {
            int c0 = kk * 2;
            uint32_t ah[2][4], al[2][4];
#pragma unroll
            for (int mt = 0; mt < 2; mt++) {
                ldsm4(ah[mt], addrA(st,        wm + mt * 16, c0));
                ldsm4(al[mt], addrA(st + 8192, wm + mt * 16, c0));
            }
            uint32_t b1[8], b2[8];
            ldsm4(b1,     addrB(st + 16384, wn,      c0));
            ldsm4(b1 + 4, addrB(st + 16384, wn + 16, c0));
            ldsm4(b2,     addrB(st + 20480, wn,      c0));
            ldsm4(b2 + 4, addrB(st + 20480, wn + 16, c0));
#pragma unroll
            for (int mt = 0; mt < 2; mt++)
#pragma unroll
                for (int nt = 0; nt < 4; nt++) {
                    mma_f16(acc1[mt][nt], ah[mt], &b1[nt * 2]);
                    mma_f16(acc2[mt][nt], ah[mt], &b2[nt * 2]);
                }
#pragma unroll
            for (int mt = 0; mt < 2; mt++)
#pragma unroll
                for (int nt = 0; nt < 4; nt++) {
                    mma_f16(acc1[mt][nt], al[mt], &b1[nt * 2]);
                    mma_f16(acc2[mt][nt], al[mt], &b2[nt * 2]);
                }
        }
    }

    // epilogue
    const int lr = lane >> 2, lc = lane & 3;
    float dbv[4][2], avv[4][2], bbv[4][2];
#pragma unroll
    for (int nt = 0; nt < 4; nt++)
#pragma unroll
        for (int j = 0; j < 2; j++) {
            int n = n0 + wn + nt * 8 + lc * 2 + j;
            dbv[nt][j] = __ldg(&dbias[n]);
            avv[nt][j] = __ldg(&Avec[n]);
            bbv[nt][j] = __ldg(&Bb[n]);
        }
#pragma unroll
    for (int mt = 0; mt < 2; mt++)
#pragma unroll
        for (int half = 0; half < 2; half++) {
            int m = m0 + wm + mt * 16 + half * 8 + lr;
            size_t rowo = (size_t)m * DHSZ;
#pragma unroll
            for (int nt = 0; nt < 4; nt++) {
                int n = n0 + wn + nt * 8 + lc * 2;
                float2 oa, ob;
#pragma unroll
                for (int j = 0; j < 2; j++) {
                    float t1 = acc1[mt][nt][half * 2 + j] + dbv[nt][j];
                    float e = __expf(-fabsf(t1));
                    float delta = fmaxf(t1, 0.f) + __logf(1.f + e);
                    float a = __expf(delta * avv[nt][j]);
                    float b = delta * (acc2[mt][nt][half * 2 + j] + bbv[nt][j]);
                    if (j == 0) { oa.x = a; ob.x = b; } else { oa.y = a; ob.y = b; }
                }
                *(float2*)&g_Abar[rowo + n] = oa;
                *(float2*)&g_Bbar[rowo + n] = ob;
            }
        }
}

// ---------------- kernel 2: linear recurrence scan (H -> bf16 hi/lo) -------
__global__ __launch_bounds__(256) void scan_kernel()
{
    int c = blockIdx.x * 256 + threadIdx.x;   // 0..8191
    int b = c >> 10;
    int h = c & (DHSZ - 1);
    size_t base = (size_t)b * LSZ * DHSZ + h;

    float hp = 0.f;
    for (int l0 = 0; l0 < LSZ; l0 += 16) {
        float av[16], bv[16];
#pragma unroll
        for (int u = 0; u < 16; u++) {
            size_t o = base + (size_t)(l0 + u) * DHSZ;
            av[u] = g_Abar[o];
            bv[u] = g_Bbar[o];
        }
#pragma unroll
        for (int u = 0; u < 16; u++) {
            hp = fmaf(av[u], hp, bv[u]);
            size_t o = base + (size_t)(l0 + u) * DHSZ;
            __nv_bfloat16 hh = __float2bfloat16_rn(hp);
            g_Hhi[o] = hh;
            g_Hlo[o] = __float2bfloat16_rn(hp - __bfloat162float(hh));
        }
    }
}

// ---------------- kernel 3: out = h@Cw^T (bf16 3-term) + x@Dw^T (fp16 2-term)
// CTA 128x128; 8 warps 2m x 4n; warp 64x32; BK=32; 3-stage pipe.
// Stage (32KB): A0 0, A1 8192, W0 16384, W1 24576 (W1 unused in pass 2).
__global__ __launch_bounds__(256, 1)
void gemm3_kernel(const float* __restrict__ Cb, const float* __restrict__ Db,
                  float* __restrict__ out)
{
    extern __shared__ char smem[];
    uint32_t sb = smem_u32(smem);
    const int t = threadIdx.x, wid = t >> 5, lane = t & 31;
    const int m0 = blockIdx.y * 128, n0 = blockIdx.x * 128;
    const int wm = (wid & 1) * 64;
    const int wn = (wid >> 1) * 32;

    float acc[4][4][4];
#pragma unroll
    for (int i = 0; i < 4; i++)
#pragma unroll
        for (int j = 0; j < 4; j++)
#pragma unroll
            for (int q = 0; q < 4; q++) acc[i][j][q] = 0.f;

    auto issue_stage = [&](int s, int kidx) {
        uint32_t st = sb + s * 32768;
        int kb = (kidx & 31) * 32;
        if (kidx < 32) {      // pass 1: h @ Cw^T, bf16 3-term
            load_tile_async<128>(st,          g_Hhi,  m0, kb);
            load_tile_async<128>(st + 8192,   g_Hlo,  m0, kb);
            load_tile_async<128>(st + 16384,  g_Cwhi, n0, kb);
            load_tile_async<128>(st + 24576,  g_Cwlo, n0, kb);
        } else {              // pass 2: x @ Dw^T, fp16 2-term
            load_tile_async<128>(st,          g_xhi, m0, kb);
            load_tile_async<128>(st + 8192,   g_xlo, m0, kb);
            load_tile_async<128>(st + 16384,  g_Dwh, n0, kb);
        }
        CP_COMMIT();
    };
    issue_stage(0, 0);
    issue_stage(1, 1);

    const int K = 64;
    for (int k = 0; k < K; k++) {
        if (k + 2 < K) CP_WAIT(1); else CP_WAIT(0);
        __syncthreads();
        if (k + 2 < K) issue_stage((k + 2) % 3, k + 2);

        uint32_t st = sb + (k % 3) * 32768;
        if (k < 32) {
            // bf16 3-term
#pragma unroll
            for (int kk = 0; kk < 2; kk++) {
                int c0 = kk * 2;
                uint32_t ah[4][4], al[4][4];
#pragma unroll
                for (int mt = 0; mt < 4; mt++) {
                    ldsm4(ah[mt], addrA(st,        wm + mt * 16, c0));
                    ldsm4(al[mt], addrA(st + 8192, wm + mt * 16, c0));
                }
                uint32_t bh[8], bl[8];
                ldsm4(bh,     addrB(st + 16384, wn,      c0));
                ldsm4(bh + 4, addrB(st + 16384, wn + 16, c0));
                ldsm4(bl,     addrB(st + 24576, wn,      c0));
                ldsm4(bl + 4, addrB(st + 24576, wn + 16, c0));
#pragma unroll
                for (int mt = 0; mt < 4; mt++)
#pragma unroll
                    for (int nt = 0; nt < 4; nt++)
                        mma_bf16(acc[mt][nt], ah[mt], &bh[nt * 2]);
#pragma unroll
                for (int mt = 0; mt < 4; mt++)
#pragma unroll
                    for (int nt = 0; nt < 4; nt++)
                        mma_bf16(acc[mt][nt], ah[mt], &bl[nt * 2]);
#pragma unroll
                for (int mt = 0; mt < 4; mt++)
#pragma unroll
                    for (int nt = 0; nt < 4; nt++)
                        mma_bf16(acc[mt][nt], al[mt], &bh[nt * 2]);
            }
        } else {
            // fp16 2-term
#pragma unroll
            for (int kk = 0; kk < 2; kk++) {
                int c0 = kk * 2;
                uint32_t ah[4][4], al[4][4];
#pragma unroll
                for (int mt = 0; mt < 4; mt++) {
                    ldsm4(ah[mt], addrA(st,        wm + mt * 16, c0));
                    ldsm4(al[mt], addrA(st + 8192, wm + mt * 16, c0));
                }
                uint32_t bh[8];
                ldsm4(bh,     addrB(st + 16384, wn,      c0));
                ldsm4(bh + 4, addrB(st + 16384, wn + 16, c0));
#pragma unroll
                for (int mt = 0; mt < 4; mt++)
#pragma unroll
                    for (int nt = 0; nt < 4; nt++)
                        mma_f16(acc[mt][nt], ah[mt], &bh[nt * 2]);
#pragma unroll
                for (int mt = 0; mt < 4; mt++)
#pragma unroll
                    for (int nt = 0; nt < 4; nt++)
                        mma_f16(acc[mt][nt], al[mt], &bh[nt * 2]);
            }
        }
    }

    const int lr = lane >> 2, lc = lane & 3;
    float biasv[4][2];
#pragma unroll
    for (int nt = 0; nt < 4; nt++)
#pragma unroll
        for (int j = 0; j < 2; j++) {
            int n = n0 + wn + nt * 8 + lc * 2 + j;
            biasv[nt][j] = __ldg(&Cb[n]) + __ldg(&Db[n]);
        }
#pragma unroll
    for (int mt = 0; mt < 4; mt++)
#pragma unroll
        for (int half = 0; half < 2; half++) {
            int m = m0 + wm + mt * 16 + half * 8 + lr;
            size_t rowo = (size_t)m * DMSZ;
#pragma unroll
            for (int nt = 0; nt < 4; nt++) {
                int n = n0 + wn + nt * 8 + lc * 2;
                float2 o;
                o.x = acc[mt][nt][half * 2 + 0] + biasv[nt][0];
                o.y = acc[mt][nt][half * 2 + 1] + biasv[nt][1];
                *(float2*)&out[rowo + n] = o;
            }
        }
}

// ---------------- launch ---------------------------------------------------
// Inputs: 0:x 1:A 2:Bw 3:Bb 4:Cw 5:Cb 6:Dw 7:Db 8:dw 9:db
extern "C" void kernel_launch(void* const* d_in, const int* in_sizes, int n_in,
                              void* d_out, int out_size)
{
    const float* x    = (const float*)d_in[0];
    const float* Avec = (const float*)d_in[1];
    const float* Bw   = (const float*)d_in[2];
    const float* Bb   = (const float*)d_in[3];
    const float* Cw   = (const float*)d_in[4];
    const float* Cb   = (const float*)d_in[5];
    const float* Dw   = (const float*)d_in[6];
    const float* Db   = (const float*)d_in[7];
    const float* dw   = (const float*)d_in[8];
    const float* db   = (const float*)d_in[9];
    float* out = (float*)d_out;

    void *xhi, *xlo, *dwh, *bwh, *Dwh, *cwhi, *cwlo;
    cudaGetSymbolAddress(&xhi, g_xhi);   cudaGetSymbolAddress(&xlo, g_xlo);
    cudaGetSymbolAddress(&dwh, g_dwh);   cudaGetSymbolAddress(&bwh, g_Bwh);
    cudaGetSymbolAddress(&Dwh, g_Dwh);
    cudaGetSymbolAddress(&cwhi, g_Cwhi); cudaGetSymbolAddress(&cwlo, g_Cwlo);

    cudaFuncSetAttribute(gemm1_kernel, cudaFuncAttributeMaxDynamicSharedMemorySize, 73728);
    cudaFuncSetAttribute(gemm3_kernel, cudaFuncAttributeMaxDynamicSharedMemorySize, 98304);

    int nx4 = (MSZ * DMSZ) / 4;       // 4,194,304
    int nw4 = (DHSZ * DMSZ) / 4;      // 262,144
    convert_x_kernel<<<nx4 / 256, 256>>>(x, (__half*)xhi, (__half*)xlo, nx4);
    dim3 gw(nw4 / 256, 3);
    convert_w16_kernel<<<gw, 256>>>(dw, Bw, Dw, (__half*)dwh, (__half*)bwh, (__half*)Dwh);
    convert_cw_kernel<<<nw4 / 256, 256>>>(Cw, (__nv_bfloat16*)cwhi, (__nv_bfloat16*)cwlo);

    dim3 g1(DHSZ / 64, MSZ / 128);    // (16, 128)
    gemm1_kernel<<<g1, 256, 73728>>>(db, Bb, Avec);

    scan_kernel<<<(BSZ * DHSZ) / 256, 256>>>();

    dim3 g3(DMSZ / 128, MSZ / 128);   // (8, 128)
    gemm3_kernel<<<g3, 256, 98304>>>(Cb, Db, out);
}

// round 11
// speedup vs baseline: 1.4656x; 1.2161x over previous
#include <cuda_runtime.h>
#include <cuda_fp16.h>
#include <cuda_bf16.h>
#include <cstdint>

#define BSZ  8
#define LSZ  2048
#define DMSZ 1024
#define DHSZ 1024
#define MSZ  (BSZ * LSZ)   // 16384

// ---------------- scratch (__device__ globals; allocation-free rule) -------
// fp16 side (range-safe tensors only: x, dw, Bw, Dw)
__device__ __half g_xhi[(size_t)MSZ * DMSZ];
__device__ __half g_xlo[(size_t)MSZ * DMSZ];
__device__ __half g_dwh[DHSZ * DMSZ];
__device__ __half g_Bwh[DHSZ * DMSZ];
__device__ __half g_Dwh[DMSZ * DMSZ];
// bf16 side (wide-range h path)
__device__ __nv_bfloat16 g_Cwhi[DMSZ * DHSZ], g_Cwlo[DMSZ * DHSZ];
__device__ __nv_bfloat16 g_Hhi[(size_t)MSZ * DHSZ];
__device__ __nv_bfloat16 g_Hlo[(size_t)MSZ * DHSZ];
// fp32 intermediates
__device__ float g_Abar[(size_t)MSZ * DHSZ];
__device__ float g_Bbar[(size_t)MSZ * DHSZ];

// ---------------- helpers --------------------------------------------------
__device__ __forceinline__ uint32_t smem_u32(const void* p) {
    uint32_t a;
    asm("{ .reg .u64 t; cvta.to.shared.u64 t, %1; cvt.u32.u64 %0, t; }"
        : "=r"(a) : "l"(p));
    return a;
}

// SMEM tile: rows of 32 16-bit elems = 64B = 4 chunks of 16B.
// chunk' = chunk ^ ((row>>1)&3) -> conflict-free for ldmatrix + stores.
__device__ __forceinline__ uint32_t sw_chunk_off(int r, int c) {
    return (uint32_t)(((r << 2) | (c ^ ((r >> 1) & 3))) << 4);
}

__device__ __forceinline__ void ldsm4(uint32_t* d, uint32_t addr) {
    asm volatile("ldmatrix.sync.aligned.m8n8.x4.shared.b16 {%0,%1,%2,%3}, [%4];"
                 : "=r"(d[0]), "=r"(d[1]), "=r"(d[2]), "=r"(d[3]) : "r"(addr));
}

__device__ __forceinline__ void mma_f16(float* c, const uint32_t* a, const uint32_t* b) {
    asm volatile(
        "mma.sync.aligned.m16n8k16.row.col.f32.f16.f16.f32 "
        "{%0,%1,%2,%3}, {%4,%5,%6,%7}, {%8,%9}, {%0,%1,%2,%3};"
        : "+f"(c[0]), "+f"(c[1]), "+f"(c[2]), "+f"(c[3])
        : "r"(a[0]), "r"(a[1]), "r"(a[2]), "r"(a[3]), "r"(b[0]), "r"(b[1]));
}
__device__ __forceinline__ void mma_bf16(float* c, const uint32_t* a, const uint32_t* b) {
    asm volatile(
        "mma.sync.aligned.m16n8k16.row.col.f32.bf16.bf16.f32 "
        "{%0,%1,%2,%3}, {%4,%5,%6,%7}, {%8,%9}, {%0,%1,%2,%3};"
        : "+f"(c[0]), "+f"(c[1]), "+f"(c[2]), "+f"(c[3])
        : "r"(a[0]), "r"(a[1]), "r"(a[2]), "r"(a[3]), "r"(b[0]), "r"(b[1]));
}

__device__ __forceinline__ uint32_t addrA(uint32_t sbase, int mrow, int c0) {
    int l = threadIdx.x & 31;
    int r = mrow + (l & 15);
    int c = c0 + (l >> 4);
    return sbase + sw_chunk_off(r, c);
}
__device__ __forceinline__ uint32_t addrB(uint32_t sbase, int nrow, int c0) {
    int l = threadIdx.x & 31;
    int r = nrow + (l & 7) + ((l >> 4) << 3);
    int c = c0 + ((l >> 3) & 1);
    return sbase + sw_chunk_off(r, c);
}

// Generic 16-bit tile loader (fp16 or bf16): ROWS x 32 elems at (row0, kb).
template <int ROWS>
__device__ __forceinline__ void load_tile_async(uint32_t sbase,
                                                const void* __restrict__ g,
                                                int row0, int kb)
{
    int t = threadIdx.x;
    const char* gb = (const char*)g + ((size_t)row0 * 1024 + kb) * 2;
#pragma unroll
    for (int i = 0; i < (ROWS * 4) / 256; i++) {
        int idx = i * 256 + t;
        int r = idx >> 2;
        int c = idx & 3;
        const char* src = gb + (size_t)r * 2048 + c * 16;
        uint32_t dst = sbase + sw_chunk_off(r, c);
        asm volatile("cp.async.cg.shared.global [%0], [%1], 16;"
                     :: "r"(dst), "l"(src) : "memory");
    }
}
#define CP_COMMIT()  asm volatile("cp.async.commit_group;" ::: "memory")
#define CP_WAIT(n)   asm volatile("cp.async.wait_group %0;" :: "n"(n) : "memory")

// ---------------- prep kernels ---------------------------------------------
__global__ __launch_bounds__(256) void convert_x_kernel(
    const float* __restrict__ src, __half* __restrict__ hi,
    __half* __restrict__ lo, int n4)
{
    int i = blockIdx.x * 256 + threadIdx.x;
    if (i >= n4) return;
    float4 v = ((const float4*)src)[i];
    __half h0 = __float2half_rn(v.x), h1 = __float2half_rn(v.y);
    __half h2 = __float2half_rn(v.z), h3 = __float2half_rn(v.w);
    __half l0 = __float2half_rn(v.x - __half2float(h0));
    __half l1 = __float2half_rn(v.y - __half2float(h1));
    __half l2 = __float2half_rn(v.z - __half2float(h2));
    __half l3 = __float2half_rn(v.w - __half2float(h3));
    __half2* hp = (__half2*)(hi + (size_t)i * 4);
    __half2* lp = (__half2*)(lo + (size_t)i * 4);
    hp[0] = __halves2half2(h0, h1);
    hp[1] = __halves2half2(h2, h3);
    lp[0] = __halves2half2(l0, l1);
    lp[1] = __halves2half2(l2, l3);
}

// dw, Bw, Dw -> single fp16 (blockIdx.y selects)
__global__ __launch_bounds__(256) void convert_w16_kernel(
    const float* __restrict__ s0, const float* __restrict__ s1,
    const float* __restrict__ s2,
    __half* __restrict__ d0, __half* __restrict__ d1, __half* __restrict__ d2)
{
    const float* s;
    __half* d;
    switch (blockIdx.y) {
        case 0:  s = s0; d = d0; break;
        case 1:  s = s1; d = d1; break;
        default: s = s2; d = d2; break;
    }
    int i = blockIdx.x * 256 + threadIdx.x;
    float4 v = ((const float4*)s)[i];
    __half2* dp = (__half2*)(d + (size_t)i * 4);
    dp[0] = __halves2half2(__float2half_rn(v.x), __float2half_rn(v.y));
    dp[1] = __halves2half2(__float2half_rn(v.z), __float2half_rn(v.w));
}

// Cw -> bf16 hi/lo
__global__ __launch_bounds__(256) void convert_cw_kernel(
    const float* __restrict__ src, __nv_bfloat16* __restrict__ hi,
    __nv_bfloat16* __restrict__ lo)
{
    int i = blockIdx.x * 256 + threadIdx.x;
    float4 v = ((const float4*)src)[i];
    __nv_bfloat16 h0 = __float2bfloat16_rn(v.x);
    __nv_bfloat16 h1 = __float2bfloat16_rn(v.y);
    __nv_bfloat16 h2 = __float2bfloat16_rn(v.z);
    __nv_bfloat16 h3 = __float2bfloat16_rn(v.w);
    __nv_bfloat16 l0 = __float2bfloat16_rn(v.x - __bfloat162float(h0));
    __nv_bfloat16 l1 = __float2bfloat16_rn(v.y - __bfloat162float(h1));
    __nv_bfloat16 l2 = __float2bfloat16_rn(v.z - __bfloat162float(h2));
    __nv_bfloat16 l3 = __float2bfloat16_rn(v.w - __bfloat162float(h3));
    __nv_bfloat162* hp = (__nv_bfloat162*)(hi + (size_t)i * 4);
    __nv_bfloat162* lp = (__nv_bfloat162*)(lo + (size_t)i * 4);
    hp[0] = __halves2bfloat162(h0, h1);
    hp[1] = __halves2bfloat162(h2, h3);
    lp[0] = __halves2bfloat162(l0, l1);
    lp[1] = __halves2bfloat162(l2, l3);
}

// ---------------- kernel 1: dual GEMM (x@dw^T, x@Bw^T) + SSM epilogue ------
// fp16 2-term. CTA 128x64; 8 warps 4m x 2n; warp 32x32; BK=32; 3-stage pipe.
// __launch_bounds__(256, 2): cap regs at 128 so 2 CTAs co-reside per SM.
// Stage (24KB): xh 0, xl 8192, dw 16384, Bw 20480.
__global__ __launch_bounds__(256, 2)
void gemm1_kernel(const float* __restrict__ dbias, const float* __restrict__ Bb,
                  const float* __restrict__ Avec)
{
    extern __shared__ char smem[];
    uint32_t sb = smem_u32(smem);
    const int t = threadIdx.x, wid = t >> 5, lane = t & 31;
    const int m0 = blockIdx.y * 128, n0 = blockIdx.x * 64;
    const int wm = (wid & 3) * 32;
    const int wn = (wid >> 2) * 32;

    float acc1[2][4][4], acc2[2][4][4];
#pragma unroll
    for (int i = 0; i < 2; i++)
#pragma unroll
        for (int j = 0; j < 4; j++)
#pragma unroll
            for (int q = 0; q < 4; q++) { acc1[i][j][q] = 0.f; acc2[i][j][q] = 0.f; }

    auto issue_stage = [&](int s, int kidx) {
        uint32_t st = sb + s * 24576;
        int kb = kidx * 32;
        load_tile_async<128>(st,          g_xhi, m0, kb);
        load_tile_async<128>(st + 8192,   g_xlo, m0, kb);
        load_tile_async<64> (st + 16384,  g_dwh, n0, kb);
        load_tile_async<64> (st + 20480,  g_Bwh, n0, kb);
        CP_COMMIT();
    };
    issue_stage(0, 0);
    issue_stage(1, 1);

    const int K = 32;
    for (int k = 0; k < K; k++) {
        if (k + 2 < K) CP_WAIT(1); else CP_WAIT(0);
        __syncthreads();
        if (k + 2 < K) issue_stage((k + 2) % 3, k + 2);

        uint32_t st = sb + (k % 3) * 24576;
#pragma unroll
        for (int kk = 0; kk < 2; kk++) {
            int c0 = kk * 2;
            uint32_t ah[2][4], al[2][4];
#pragma unroll
            for (int mt = 0; mt < 2; mt++) {
                ldsm4(ah[mt], addrA(st,        wm + mt * 16, c0));
                ldsm4(al[mt], addrA(st + 8192, wm + mt * 16, c0));
            }
            uint32_t b1[8], b2[8];
            ldsm4(b1,     addrB(st + 16384, wn,      c0));
            ldsm4(b1 + 4, addrB(st + 16384, wn + 16, c0));
            ldsm4(b2,     addrB(st + 20480, wn,      c0));
            ldsm4(b2 + 4, addrB(st + 20480, wn + 16, c0));
#pragma unroll
            for (int mt = 0; mt < 2; mt++)
#pragma unroll
                for (int nt = 0; nt < 4; nt++) {
                    mma_f16(acc1[mt][nt], ah[mt], &b1[nt * 2]);
                    mma_f16(acc2[mt][nt], ah[mt], &b2[nt * 2]);
                }
#pragma unroll
            for (int mt = 0; mt < 2; mt++)
#pragma unroll
                for (int nt = 0; nt < 4; nt++) {
                    mma_f16(acc1[mt][nt], al[mt], &b1[nt * 2]);
                    mma_f16(acc2[mt][nt], al[mt], &b2[nt * 2]);
                }
        }
    }

    // epilogue
    const int lr = lane >> 2, lc = lane & 3;
    float dbv[4][2], avv[4][2], bbv[4][2];
#pragma unroll
    for (int nt = 0; nt < 4; nt++)
#pragma unroll
        for (int j = 0; j < 2; j++) {
            int n = n0 + wn + nt * 8 + lc * 2 + j;
            dbv[nt][j] = __ldg(&dbias[n]);
            avv[nt][j] = __ldg(&Avec[n]);
            bbv[nt][j] = __ldg(&Bb[n]);
        }
#pragma unroll
    for (int mt = 0; mt < 2; mt++)
#pragma unroll
        for (int half = 0; half < 2; half++) {
            int m = m0 + wm + mt * 16 + half * 8 + lr;
            size_t rowo = (size_t)m * DHSZ;
#pragma unroll
            for (int nt = 0; nt < 4; nt++) {
                int n = n0 + wn + nt * 8 + lc * 2;
                float2 oa, ob;
#pragma unroll
                for (int j = 0; j < 2; j++) {
                    float t1 = acc1[mt][nt][half * 2 + j] + dbv[nt][j];
                    float e = __expf(-fabsf(t1));
                    float delta = fmaxf(t1, 0.f) + __logf(1.f + e);
                    float a = __expf(delta * avv[nt][j]);
                    float b = delta * (acc2[mt][nt][half * 2 + j] + bbv[nt][j]);
                    if (j == 0) { oa.x = a; ob.x = b; } else { oa.y = a; ob.y = b; }
                }
                *(float2*)&g_Abar[rowo + n] = oa;
                *(float2*)&g_Bbar[rowo + n] = ob;
            }
        }
}

// ---------------- kernel 2: linear recurrence scan (H -> bf16 hi/lo) -------
__global__ __launch_bounds__(256) void scan_kernel()
{
    int c = blockIdx.x * 256 + threadIdx.x;   // 0..8191
    int b = c >> 10;
    int h = c & (DHSZ - 1);
    size_t base = (size_t)b * LSZ * DHSZ + h;

    float hp = 0.f;
    for (int l0 = 0; l0 < LSZ; l0 += 16) {
        float av[16], bv[16];
#pragma unroll
        for (int u = 0; u < 16; u++) {
            size_t o = base + (size_t)(l0 + u) * DHSZ;
            av[u] = g_Abar[o];
            bv[u] = g_Bbar[o];
        }
#pragma unroll
        for (int u = 0; u < 16; u++) {
            hp = fmaf(av[u], hp, bv[u]);
            size_t o = base + (size_t)(l0 + u) * DHSZ;
            __nv_bfloat16 hh = __float2bfloat16_rn(hp);
            g_Hhi[o] = hh;
            g_Hlo[o] = __float2bfloat16_rn(hp - __bfloat162float(hh));
        }
    }
}

// ---------------- kernel 3: out = h@Cw^T (bf16 3-term) + x@Dw^T (fp16 2-term)
// CTA 128x128; 8 warps 2m x 4n; warp 64x32; BK=32; 3-stage pipe.
// __launch_bounds__(256, 2): cap regs at 128 so 2 CTAs co-reside per SM.
// Stage (32KB): A0 0, A1 8192, W0 16384, W1 24576 (W1 unused in pass 2).
__global__ __launch_bounds__(256, 2)
void gemm3_kernel(const float* __restrict__ Cb, const float* __restrict__ Db,
                  float* __restrict__ out)
{
    extern __shared__ char smem[];
    uint32_t sb = smem_u32(smem);
    const int t = threadIdx.x, wid = t >> 5, lane = t & 31;
    const int m0 = blockIdx.y * 128, n0 = blockIdx.x * 128;
    const int wm = (wid & 1) * 64;
    const int wn = (wid >> 1) * 32;

    float acc[4][4][4];
#pragma unroll
    for (int i = 0; i < 4; i++)
#pragma unroll
        for (int j = 0; j < 4; j++)
#pragma unroll
            for (int q = 0; q < 4; q++) acc[i][j][q] = 0.f;

    auto issue_stage = [&](int s, int kidx) {
        uint32_t st = sb + s * 32768;
        int kb = (kidx & 31) * 32;
        if (kidx < 32) {      // pass 1: h @ Cw^T, bf16 3-term
            load_tile_async<128>(st,          g_Hhi,  m0, kb);
            load_tile_async<128>(st + 8192,   g_Hlo,  m0, kb);
            load_tile_async<128>(st + 16384,  g_Cwhi, n0, kb);
            load_tile_async<128>(st + 24576,  g_Cwlo, n0, kb);
        } else {              // pass 2: x @ Dw^T, fp16 2-term
            load_tile_async<128>(st,          g_xhi, m0, kb);
            load_tile_async<128>(st + 8192,   g_xlo, m0, kb);
            load_tile_async<128>(st + 16384,  g_Dwh, n0, kb);
        }
        CP_COMMIT();
    };
    issue_stage(0, 0);
    issue_stage(1, 1);

    const int K = 64;
    for (int k = 0; k < K; k++) {
        if (k + 2 < K) CP_WAIT(1); else CP_WAIT(0);
        __syncthreads();
        if (k + 2 < K) issue_stage((k + 2) % 3, k + 2);

        uint32_t st = sb + (k % 3) * 32768;
        if (k < 32) {
            // bf16 3-term
#pragma unroll
            for (int kk = 0; kk < 2; kk++) {
                int c0 = kk * 2;
                uint32_t ah[4][4], al[4][4];
#pragma unroll
                for (int mt = 0; mt < 4; mt++) {
                    ldsm4(ah[mt], addrA(st,        wm + mt * 16, c0));
                    ldsm4(al[mt], addrA(st + 8192, wm + mt * 16, c0));
                }
                uint32_t bh[8], bl[8];
                ldsm4(bh,     addrB(st + 16384, wn,      c0));
                ldsm4(bh + 4, addrB(st + 16384, wn + 16, c0));
                ldsm4(bl,     addrB(st + 24576, wn,      c0));
                ldsm4(bl + 4, addrB(st + 24576, wn + 16, c0));
#pragma unroll
                for (int mt = 0; mt < 4; mt++)
#pragma unroll
                    for (int nt = 0; nt < 4; nt++)
                        mma_bf16(acc[mt][nt], ah[mt], &bh[nt * 2]);
#pragma unroll
                for (int mt = 0; mt < 4; mt++)
#pragma unroll
                    for (int nt = 0; nt < 4; nt++)
                        mma_bf16(acc[mt][nt], ah[mt], &bl[nt * 2]);
#pragma unroll
                for (int mt = 0; mt < 4; mt++)
#pragma unroll
                    for (int nt = 0; nt < 4; nt++)
                        mma_bf16(acc[mt][nt], al[mt], &bh[nt * 2]);
            }
        } else {
            // fp16 2-term
#pragma unroll
            for (int kk = 0; kk < 2; kk++) {
                int c0 = kk * 2;
                uint32_t ah[4][4], al[4][4];
#pragma unroll
                for (int mt = 0; mt < 4; mt++) {
                    ldsm4(ah[mt], addrA(st,        wm + mt * 16, c0));
                    ldsm4(al[mt], addrA(st + 8192, wm + mt * 16, c0));
                }
                uint32_t bh[8];
                ldsm4(bh,     addrB(st + 16384, wn,      c0));
                ldsm4(bh + 4, addrB(st + 16384, wn + 16, c0));
#pragma unroll
                for (int mt = 0; mt < 4; mt++)
#pragma unroll
                    for (int nt = 0; nt < 4; nt++)
                        mma_f16(acc[mt][nt], ah[mt], &bh[nt * 2]);
#pragma unroll
                for (int mt = 0; mt < 4; mt++)
#pragma unroll
                    for (int nt = 0; nt < 4; nt++)
                        mma_f16(acc[mt][nt], al[mt], &bh[nt * 2]);
            }
        }
    }

    const int lr = lane >> 2, lc = lane & 3;
    float biasv[4][2];
#pragma unroll
    for (int nt = 0; nt < 4; nt++)
#pragma unroll
        for (int j = 0; j < 2; j++) {
            int n = n0 + wn + nt * 8 + lc * 2 + j;
            biasv[nt][j] = __ldg(&Cb[n]) + __ldg(&Db[n]);
        }
#pragma unroll
    for (int mt = 0; mt < 4; mt++)
#pragma unroll
        for (int half = 0; half < 2; half++) {
            int m = m0 + wm + mt * 16 + half * 8 + lr;
            size_t rowo = (size_t)m * DMSZ;
#pragma unroll
            for (int nt = 0; nt < 4; nt++) {
                int n = n0 + wn + nt * 8 + lc * 2;
                float2 o;
                o.x = acc[mt][nt][half * 2 + 0] + biasv[nt][0];
                o.y = acc[mt][nt][half * 2 + 1] + biasv[nt][1];
                *(float2*)&out[rowo + n] = o;
            }
        }
}

// ---------------- launch ---------------------------------------------------
// Inputs: 0:x 1:A 2:Bw 3:Bb 4:Cw 5:Cb 6:Dw 7:Db 8:dw 9:db
extern "C" void kernel_launch(void* const* d_in, const int* in_sizes, int n_in,
                              void* d_out, int out_size)
{
    const float* x    = (const float*)d_in[0];
    const float* Avec = (const float*)d_in[1];
    const float* Bw   = (const float*)d_in[2];
    const float* Bb   = (const float*)d_in[3];
    const float* Cw   = (const float*)d_in[4];
    const float* Cb   = (const float*)d_in[5];
    const float* Dw   = (const float*)d_in[6];
    const float* Db   = (const float*)d_in[7];
    const float* dw   = (const float*)d_in[8];
    const float* db   = (const float*)d_in[9];
    float* out = (float*)d_out;

    void *xhi, *xlo, *dwh, *bwh, *Dwh, *cwhi, *cwlo;
    cudaGetSymbolAddress(&xhi, g_xhi);   cudaGetSymbolAddress(&xlo, g_xlo);
    cudaGetSymbolAddress(&dwh, g_dwh);   cudaGetSymbolAddress(&bwh, g_Bwh);
    cudaGetSymbolAddress(&Dwh, g_Dwh);
    cudaGetSymbolAddress(&cwhi, g_Cwhi); cudaGetSymbolAddress(&cwlo, g_Cwlo);

    cudaFuncSetAttribute(gemm1_kernel, cudaFuncAttributeMaxDynamicSharedMemorySize, 73728);
    cudaFuncSetAttribute(gemm3_kernel, cudaFuncAttributeMaxDynamicSharedMemorySize, 98304);

    int nx4 = (MSZ * DMSZ) / 4;       // 4,194,304
    int nw4 = (DHSZ * DMSZ) / 4;      // 262,144
    convert_x_kernel<<<nx4 / 256, 256>>>(x, (__half*)xhi, (__half*)xlo, nx4);
    dim3 gw(nw4 / 256, 3);
    convert_w16_kernel<<<gw, 256>>>(dw, Bw, Dw, (__half*)dwh, (__half*)bwh, (__half*)Dwh);
    convert_cw_kernel<<<nw4 / 256, 256>>>(Cw, (__nv_bfloat16*)cwhi, (__nv_bfloat16*)cwlo);

    dim3 g1(DHSZ / 64, MSZ / 128);    // (16, 128)
    gemm1_kernel<<<g1, 256, 73728>>>(db, Bb, Avec);

    scan_kernel<<<(BSZ * DHSZ) / 256, 256>>>();

    dim3 g3(DMSZ / 128, MSZ / 128);   // (8, 128)
    gemm3_kernel<<<g3, 256, 98304>>>(Cb, Db, out);
}

// round 12
// speedup vs baseline: 1.9198x; 1.3099x over previous
#include <cuda_runtime.h>
#include <cuda_fp16.h>
#include <cuda_bf16.h>
#include <cstdint>

#define BSZ  8
#define LSZ  2048
#define DMSZ 1024
#define DHSZ 1024
#define MSZ  (BSZ * LSZ)   // 16384

// ---------------- scratch (__device__ globals; allocation-free rule) -------
// fp16 side (range-safe tensors only: x, dw, Bw, Dw)
__device__ __half g_xh[(size_t)MSZ * DMSZ];
__device__ __half g_dwh[DHSZ * DMSZ];
__device__ __half g_Bwh[DHSZ * DMSZ];
__device__ __half g_Dwh[DMSZ * DMSZ];
// bf16 side (wide-range h path)
__device__ __nv_bfloat16 g_Cwhi[DMSZ * DHSZ], g_Cwlo[DMSZ * DHSZ];
__device__ __nv_bfloat16 g_Hhi[(size_t)MSZ * DHSZ];
__device__ __nv_bfloat16 g_Hlo[(size_t)MSZ * DHSZ];
// fp32 intermediates
__device__ float g_Abar[(size_t)MSZ * DHSZ];
__device__ float g_Bbar[(size_t)MSZ * DHSZ];

// ---------------- helpers --------------------------------------------------
__device__ __forceinline__ uint32_t smem_u32(const void* p) {
    uint32_t a;
    asm("{ .reg .u64 t; cvta.to.shared.u64 t, %1; cvt.u32.u64 %0, t; }"
        : "=r"(a) : "l"(p));
    return a;
}

// SMEM tile: rows of 32 16-bit elems = 64B = 4 chunks of 16B.
// chunk' = chunk ^ ((row>>1)&3) -> conflict-free for ldmatrix + stores.
__device__ __forceinline__ uint32_t sw_chunk_off(int r, int c) {
    return (uint32_t)(((r << 2) | (c ^ ((r >> 1) & 3))) << 4);
}

__device__ __forceinline__ void ldsm4(uint32_t* d, uint32_t addr) {
    asm volatile("ldmatrix.sync.aligned.m8n8.x4.shared.b16 {%0,%1,%2,%3}, [%4];"
                 : "=r"(d[0]), "=r"(d[1]), "=r"(d[2]), "=r"(d[3]) : "r"(addr));
}

__device__ __forceinline__ void mma_f16(float* c, const uint32_t* a, const uint32_t* b) {
    asm volatile(
        "mma.sync.aligned.m16n8k16.row.col.f32.f16.f16.f32 "
        "{%0,%1,%2,%3}, {%4,%5,%6,%7}, {%8,%9}, {%0,%1,%2,%3};"
        : "+f"(c[0]), "+f"(c[1]), "+f"(c[2]), "+f"(c[3])
        : "r"(a[0]), "r"(a[1]), "r"(a[2]), "r"(a[3]), "r"(b[0]), "r"(b[1]));
}
__device__ __forceinline__ void mma_bf16(float* c, const uint32_t* a, const uint32_t* b) {
    asm volatile(
        "mma.sync.aligned.m16n8k16.row.col.f32.bf16.bf16.f32 "
        "{%0,%1,%2,%3}, {%4,%5,%6,%7}, {%8,%9}, {%0,%1,%2,%3};"
        : "+f"(c[0]), "+f"(c[1]), "+f"(c[2]), "+f"(c[3])
        : "r"(a[0]), "r"(a[1]), "r"(a[2]), "r"(a[3]), "r"(b[0]), "r"(b[1]));
}

__device__ __forceinline__ uint32_t addrA(uint32_t sbase, int mrow, int c0) {
    int l = threadIdx.x & 31;
    int r = mrow + (l & 15);
    int c = c0 + (l >> 4);
    return sbase + sw_chunk_off(r, c);
}
__device__ __forceinline__ uint32_t addrB(uint32_t sbase, int nrow, int c0) {
    int l = threadIdx.x & 31;
    int r = nrow + (l & 7) + ((l >> 4) << 3);
    int c = c0 + ((l >> 3) & 1);
    return sbase + sw_chunk_off(r, c);
}

// Generic 16-bit tile loader (fp16 or bf16): ROWS x 32 elems at (row0, kb).
template <int ROWS>
__device__ __forceinline__ void load_tile_async(uint32_t sbase,
                                                const void* __restrict__ g,
                                                int row0, int kb)
{
    int t = threadIdx.x;
    const char* gb = (const char*)g + ((size_t)row0 * 1024 + kb) * 2;
#pragma unroll
    for (int i = 0; i < (ROWS * 4) / 256; i++) {
        int idx = i * 256 + t;
        int r = idx >> 2;
        int c = idx & 3;
        const char* src = gb + (size_t)r * 2048 + c * 16;
        uint32_t dst = sbase + sw_chunk_off(r, c);
        asm volatile("cp.async.cg.shared.global [%0], [%1], 16;"
                     :: "r"(dst), "l"(src) : "memory");
    }
}
#define CP_COMMIT()  asm volatile("cp.async.commit_group;" ::: "memory")
#define CP_WAIT(n)   asm volatile("cp.async.wait_group %0;" :: "n"(n) : "memory")

// ---------------- prep kernels ---------------------------------------------
// x -> single fp16
__global__ __launch_bounds__(256) void convert_x_kernel(
    const float* __restrict__ src, __half* __restrict__ dst, int n4)
{
    int i = blockIdx.x * 256 + threadIdx.x;
    if (i >= n4) return;
    float4 v = ((const float4*)src)[i];
    __half2* dp = (__half2*)(dst + (size_t)i * 4);
    dp[0] = __halves2half2(__float2half_rn(v.x), __float2half_rn(v.y));
    dp[1] = __halves2half2(__float2half_rn(v.z), __float2half_rn(v.w));
}

// dw, Bw, Dw -> single fp16 (blockIdx.y selects)
__global__ __launch_bounds__(256) void convert_w16_kernel(
    const float* __restrict__ s0, const float* __restrict__ s1,
    const float* __restrict__ s2,
    __half* __restrict__ d0, __half* __restrict__ d1, __half* __restrict__ d2)
{
    const float* s;
    __half* d;
    switch (blockIdx.y) {
        case 0:  s = s0; d = d0; break;
        case 1:  s = s1; d = d1; break;
        default: s = s2; d = d2; break;
    }
    int i = blockIdx.x * 256 + threadIdx.x;
    float4 v = ((const float4*)s)[i];
    __half2* dp = (__half2*)(d + (size_t)i * 4);
    dp[0] = __halves2half2(__float2half_rn(v.x), __float2half_rn(v.y));
    dp[1] = __halves2half2(__float2half_rn(v.z), __float2half_rn(v.w));
}

// Cw -> bf16 hi/lo
__global__ __launch_bounds__(256) void convert_cw_kernel(
    const float* __restrict__ src, __nv_bfloat16* __restrict__ hi,
    __nv_bfloat16* __restrict__ lo)
{
    int i = blockIdx.x * 256 + threadIdx.x;
    float4 v = ((const float4*)src)[i];
    __nv_bfloat16 h0 = __float2bfloat16_rn(v.x);
    __nv_bfloat16 h1 = __float2bfloat16_rn(v.y);
    __nv_bfloat16 h2 = __float2bfloat16_rn(v.z);
    __nv_bfloat16 h3 = __float2bfloat16_rn(v.w);
    __nv_bfloat16 l0 = __float2bfloat16_rn(v.x - __bfloat162float(h0));
    __nv_bfloat16 l1 = __float2bfloat16_rn(v.y - __bfloat162float(h1));
    __nv_bfloat16 l2 = __float2bfloat16_rn(v.z - __bfloat162float(h2));
    __nv_bfloat16 l3 = __float2bfloat16_rn(v.w - __bfloat162float(h3));
    __nv_bfloat162* hp = (__nv_bfloat162*)(hi + (size_t)i * 4);
    __nv_bfloat162* lp = (__nv_bfloat162*)(lo + (size_t)i * 4);
    hp[0] = __halves2bfloat162(h0, h1);
    hp[1] = __halves2bfloat162(h2, h3);
    lp[0] = __halves2bfloat162(l0, l1);
    lp[1] = __halves2bfloat162(l2, l3);
}

// ---------------- kernel 1: dual GEMM (x@dw^T, x@Bw^T) + SSM epilogue ------
// fp16 single-term. CTA 128x64; 8 warps 4m x 2n; warp 32x32; BK=32; 3-stage.
// Stage (16KB): xh 0, dw 8192, Bw 12288.
__global__ __launch_bounds__(256, 2)
void gemm1_kernel(const float* __restrict__ dbias, const float* __restrict__ Bb,
                  const float* __restrict__ Avec)
{
    extern __shared__ char smem[];
    uint32_t sb = smem_u32(smem);
    const int t = threadIdx.x, wid = t >> 5, lane = t & 31;
    const int m0 = blockIdx.y * 128, n0 = blockIdx.x * 64;
    const int wm = (wid & 3) * 32;
    const int wn = (wid >> 2) * 32;

    float acc1[2][4][4], acc2[2][4][4];
#pragma unroll
    for (int i = 0; i < 2; i++)
#pragma unroll
        for (int j = 0; j < 4; j++)
#pragma unroll
            for (int q = 0; q < 4; q++) { acc1[i][j][q] = 0.f; acc2[i][j][q] = 0.f; }

    auto issue_stage = [&](int s, int kidx) {
        uint32_t st = sb + s * 16384;
        int kb = kidx * 32;
        load_tile_async<128>(st,          g_xh,  m0, kb);
        load_tile_async<64> (st + 8192,   g_dwh, n0, kb);
        load_tile_async<64> (st + 12288,  g_Bwh, n0, kb);
        CP_COMMIT();
    };
    issue_stage(0, 0);
    issue_stage(1, 1);

    const int K = 32;
    for (int k = 0; k < K; k++) {
        if (k + 2 < K) CP_WAIT(1); else CP_WAIT(0);
        __syncthreads();
        if (k + 2 < K) issue_stage((k + 2) % 3, k + 2);

        uint32_t st = sb + (k % 3) * 16384;
#pragma unroll
        for (int kk = 0; kk < 2; kk++) {
            int c0 = kk * 2;
            uint32_t ah[2][4];
#pragma unroll
            for (int mt = 0; mt < 2; mt++)
                ldsm4(ah[mt], addrA(st, wm + mt * 16, c0));
            uint32_t b1[8], b2[8];
            ldsm4(b1,     addrB(st + 8192,  wn,      c0));
            ldsm4(b1 + 4, addrB(st + 8192,  wn + 16, c0));
            ldsm4(b2,     addrB(st + 12288, wn,      c0));
            ldsm4(b2 + 4, addrB(st + 12288, wn + 16, c0));
#pragma unroll
            for (int mt = 0; mt < 2; mt++)
#pragma unroll
                for (int nt = 0; nt < 4; nt++) {
                    mma_f16(acc1[mt][nt], ah[mt], &b1[nt * 2]);
                    mma_f16(acc2[mt][nt], ah[mt], &b2[nt * 2]);
                }
        }
    }

    // epilogue
    const int lr = lane >> 2, lc = lane & 3;
    float dbv[4][2], avv[4][2], bbv[4][2];
#pragma unroll
    for (int nt = 0; nt < 4; nt++)
#pragma unroll
        for (int j = 0; j < 2; j++) {
            int n = n0 + wn + nt * 8 + lc * 2 + j;
            dbv[nt][j] = __ldg(&dbias[n]);
            avv[nt][j] = __ldg(&Avec[n]);
            bbv[nt][j] = __ldg(&Bb[n]);
        }
#pragma unroll
    for (int mt = 0; mt < 2; mt++)
#pragma unroll
        for (int half = 0; half < 2; half++) {
            int m = m0 + wm + mt * 16 + half * 8 + lr;
            size_t rowo = (size_t)m * DHSZ;
#pragma unroll
            for (int nt = 0; nt < 4; nt++) {
                int n = n0 + wn + nt * 8 + lc * 2;
                float2 oa, ob;
#pragma unroll
                for (int j = 0; j < 2; j++) {
                    float t1 = acc1[mt][nt][half * 2 + j] + dbv[nt][j];
                    float e = __expf(-fabsf(t1));
                    float delta = fmaxf(t1, 0.f) + __logf(1.f + e);
                    float a = __expf(delta * avv[nt][j]);
                    float b = delta * (acc2[mt][nt][half * 2 + j] + bbv[nt][j]);
                    if (j == 0) { oa.x = a; ob.x = b; } else { oa.y = a; ob.y = b; }
                }
                *(float2*)&g_Abar[rowo + n] = oa;
                *(float2*)&g_Bbar[rowo + n] = ob;
            }
        }
}

// ---------------- kernel 2: linear recurrence scan (H -> bf16 hi/lo) -------
__global__ __launch_bounds__(256) void scan_kernel()
{
    int c = blockIdx.x * 256 + threadIdx.x;   // 0..8191
    int b = c >> 10;
    int h = c & (DHSZ - 1);
    size_t base = (size_t)b * LSZ * DHSZ + h;

    float hp = 0.f;
    for (int l0 = 0; l0 < LSZ; l0 += 16) {
        float av[16], bv[16];
#pragma unroll
        for (int u = 0; u < 16; u++) {
            size_t o = base + (size_t)(l0 + u) * DHSZ;
            av[u] = g_Abar[o];
            bv[u] = g_Bbar[o];
        }
#pragma unroll
        for (int u = 0; u < 16; u++) {
            hp = fmaf(av[u], hp, bv[u]);
            size_t o = base + (size_t)(l0 + u) * DHSZ;
            __nv_bfloat16 hh = __float2bfloat16_rn(hp);
            g_Hhi[o] = hh;
            g_Hlo[o] = __float2bfloat16_rn(hp - __bfloat162float(hh));
        }
    }
}

// ---------------- kernel 3: out = h@Cw^T (bf16 3-term) + x@Dw^T (fp16 1-term)
// CTA 128x128; 8 warps 2m x 4n; warp 64x32; BK=32; 3-stage pipe.
// Stage (32KB): A0 0, A1 8192, W0 16384, W1 24576 (A1/W1 unused in pass 2).
__global__ __launch_bounds__(256, 2)
void gemm3_kernel(const float* __restrict__ Cb, const float* __restrict__ Db,
                  float* __restrict__ out)
{
    extern __shared__ char smem[];
    uint32_t sb = smem_u32(smem);
    const int t = threadIdx.x, wid = t >> 5, lane = t & 31;
    const int m0 = blockIdx.y * 128, n0 = blockIdx.x * 128;
    const int wm = (wid & 1) * 64;
    const int wn = (wid >> 1) * 32;

    float acc[4][4][4];
#pragma unroll
    for (int i = 0; i < 4; i++)
#pragma unroll
        for (int j = 0; j < 4; j++)
#pragma unroll
            for (int q = 0; q < 4; q++) acc[i][j][q] = 0.f;

    auto issue_stage = [&](int s, int kidx) {
        uint32_t st = sb + s * 32768;
        int kb = (kidx & 31) * 32;
        if (kidx < 32) {      // pass 1: h @ Cw^T, bf16 3-term
            load_tile_async<128>(st,          g_Hhi,  m0, kb);
            load_tile_async<128>(st + 8192,   g_Hlo,  m0, kb);
            load_tile_async<128>(st + 16384,  g_Cwhi, n0, kb);
            load_tile_async<128>(st + 24576,  g_Cwlo, n0, kb);
        } else {              // pass 2: x @ Dw^T, fp16 single-term
            load_tile_async<128>(st,          g_xh,  m0, kb);
            load_tile_async<128>(st + 16384,  g_Dwh, n0, kb);
        }
        CP_COMMIT();
    };
    issue_stage(0, 0);
    issue_stage(1, 1);

    const int K = 64;
    for (int k = 0; k < K; k++) {
        if (k + 2 < K) CP_WAIT(1); else CP_WAIT(0);
        __syncthreads();
        if (k + 2 < K) issue_stage((k + 2) % 3, k + 2);

        uint32_t st = sb + (k % 3) * 32768;
        if (k < 32) {
            // bf16 3-term
#pragma unroll
            for (int kk = 0; kk < 2; kk++) {
                int c0 = kk * 2;
                uint32_t ah[4][4], al[4][4];
#pragma unroll
                for (int mt = 0; mt < 4; mt++) {
                    ldsm4(ah[mt], addrA(st,        wm + mt * 16, c0));
                    ldsm4(al[mt], addrA(st + 8192, wm + mt * 16, c0));
                }
                uint32_t bh[8], bl[8];
                ldsm4(bh,     addrB(st + 16384, wn,      c0));
                ldsm4(bh + 4, addrB(st + 16384, wn + 16, c0));
                ldsm4(bl,     addrB(st + 24576, wn,      c0));
                ldsm4(bl + 4, addrB(st + 24576, wn + 16, c0));
#pragma unroll
                for (int mt = 0; mt < 4; mt++)
#pragma unroll
                    for (int nt = 0; nt < 4; nt++)
                        mma_bf16(acc[mt][nt], ah[mt], &bh[nt * 2]);
#pragma unroll
                for (int mt = 0; mt < 4; mt++)
#pragma unroll
                    for (int nt = 0; nt < 4; nt++)
                        mma_bf16(acc[mt][nt], ah[mt], &bl[nt * 2]);
#pragma unroll
                for (int mt = 0; mt < 4; mt++)
#pragma unroll
                    for (int nt = 0; nt < 4; nt++)
                        mma_bf16(acc[mt][nt], al[mt], &bh[nt * 2]);
            }
        } else {
            // fp16 single-term
#pragma unroll
            for (int kk = 0; kk < 2; kk++) {
                int c0 = kk * 2;
                uint32_t ah[4][4];
#pragma unroll
                for (int mt = 0; mt < 4; mt++)
                    ldsm4(ah[mt], addrA(st, wm + mt * 16, c0));
                uint32_t bh[8];
                ldsm4(bh,     addrB(st + 16384, wn,      c0));
                ldsm4(bh + 4, addrB(st + 16384, wn + 16, c0));
#pragma unroll
                for (int mt = 0; mt < 4; mt++)
#pragma unroll
                    for (int nt = 0; nt < 4; nt++)
                        mma_f16(acc[mt][nt], ah[mt], &bh[nt * 2]);
            }
        }
    }

    const int lr = lane >> 2, lc = lane & 3;
    float biasv[4][2];
#pragma unroll
    for (int nt = 0; nt < 4; nt++)
#pragma unroll
        for (int j = 0; j < 2; j++) {
            int n = n0 + wn + nt * 8 + lc * 2 + j;
            biasv[nt][j] = __ldg(&Cb[n]) + __ldg(&Db[n]);
        }
#pragma unroll
    for (int mt = 0; mt < 4; mt++)
#pragma unroll
        for (int half = 0; half < 2; half++) {
            int m = m0 + wm + mt * 16 + half * 8 + lr;
            size_t rowo = (size_t)m * DMSZ;
#pragma unroll
            for (int nt = 0; nt < 4; nt++) {
                int n = n0 + wn + nt * 8 + lc * 2;
                float2 o;
                o.x = acc[mt][nt][half * 2 + 0] + biasv[nt][0];
                o.y = acc[mt][nt][half * 2 + 1] + biasv[nt][1];
                *(float2*)&out[rowo + n] = o;
            }
        }
}

// ---------------- launch ---------------------------------------------------
// Inputs: 0:x 1:A 2:Bw 3:Bb 4:Cw 5:Cb 6:Dw 7:Db 8:dw 9:db
extern "C" void kernel_launch(void* const* d_in, const int* in_sizes, int n_in,
                              void* d_out, int out_size)
{
    const float* x    = (const float*)d_in[0];
    const float* Avec = (const float*)d_in[1];
    const float* Bw   = (const float*)d_in[2];
    const float* Bb   = (const float*)d_in[3];
    const float* Cw   = (const float*)d_in[4];
    const float* Cb   = (const float*)d_in[5];
    const float* Dw   = (const float*)d_in[6];
    const float* Db   = (const float*)d_in[7];
    const float* dw   = (const float*)d_in[8];
    const float* db   = (const float*)d_in[9];
    float* out = (float*)d_out;

    void *xh, *dwh, *bwh, *Dwh, *cwhi, *cwlo;
    cudaGetSymbolAddress(&xh, g_xh);
    cudaGetSymbolAddress(&dwh, g_dwh);   cudaGetSymbolAddress(&bwh, g_Bwh);
    cudaGetSymbolAddress(&Dwh, g_Dwh);
    cudaGetSymbolAddress(&cwhi, g_Cwhi); cudaGetSymbolAddress(&cwlo, g_Cwlo);

    cudaFuncSetAttribute(gemm1_kernel, cudaFuncAttributeMaxDynamicSharedMemorySize, 49152);
    cudaFuncSetAttribute(gemm3_kernel, cudaFuncAttributeMaxDynamicSharedMemorySize, 98304);

    int nx4 = (MSZ * DMSZ) / 4;       // 4,194,304
    int nw4 = (DHSZ * DMSZ) / 4;      // 262,144
    convert_x_kernel<<<nx4 / 256, 256>>>(x, (__half*)xh, nx4);
    dim3 gw(nw4 / 256, 3);
    convert_w16_kernel<<<gw, 256>>>(dw, Bw, Dw, (__half*)dwh, (__half*)bwh, (__half*)Dwh);
    convert_cw_kernel<<<nw4 / 256, 256>>>(Cw, (__nv_bfloat16*)cwhi, (__nv_bfloat16*)cwlo);

    dim3 g1(DHSZ / 64, MSZ / 128);    // (16, 128)
    gemm1_kernel<<<g1, 256, 49152>>>(db, Bb, Avec);

    scan_kernel<<<(BSZ * DHSZ) / 256, 256>>>();

    dim3 g3(DMSZ / 128, MSZ / 128);   // (8, 128)
    gemm3_kernel<<<g3, 256, 98304>>>(Cb, Db, out);
}

// round 13
// speedup vs baseline: 2.0494x; 1.0675x over previous
#include <cuda_runtime.h>
#include <cuda_fp16.h>
#include <cuda_bf16.h>
#include <cstdint>

#define BSZ  8
#define LSZ  2048
#define DMSZ 1024
#define DHSZ 1024
#define MSZ  (BSZ * LSZ)   // 16384

// ---------------- scratch (__device__ globals; allocation-free rule) -------
__device__ __half g_xh[(size_t)MSZ * DMSZ];     // x fp16
__device__ __half g_dwh[DHSZ * DMSZ];
__device__ __half g_Bwh[DHSZ * DMSZ];
__device__ __half g_Dwh[DMSZ * DMSZ];
__device__ float  g_Cwt[DMSZ * DHSZ];           // Cw tf32-rounded fp32
__device__ float  g_H[(size_t)MSZ * DHSZ];      // h tf32-rounded fp32
__device__ float  g_Abar[(size_t)MSZ * DHSZ];
__device__ float  g_Bbar[(size_t)MSZ * DHSZ];

// ---------------- helpers --------------------------------------------------
__device__ __forceinline__ uint32_t smem_u32(const void* p) {
    uint32_t a;
    asm("{ .reg .u64 t; cvta.to.shared.u64 t, %1; cvt.u32.u64 %0, t; }"
        : "=r"(a) : "l"(p));
    return a;
}

// 16-bit tiles: rows of 32 elems = 64B = 4 chunks of 16B; chunk ^= (row>>1)&3.
__device__ __forceinline__ uint32_t sw_chunk_off(int r, int c) {
    return (uint32_t)(((r << 2) | (c ^ ((r >> 1) & 3))) << 4);
}
// tf32 tiles: rows of 32 floats = 128B = 8 chunks of 16B; chunk ^= row&7.
__device__ __forceinline__ uint32_t sw8_off(int r, int c) {
    return (uint32_t)(((r << 3) | (c ^ (r & 7))) << 4);
}

__device__ __forceinline__ void ldsm4(uint32_t* d, uint32_t addr) {
    asm volatile("ldmatrix.sync.aligned.m8n8.x4.shared.b16 {%0,%1,%2,%3}, [%4];"
                 : "=r"(d[0]), "=r"(d[1]), "=r"(d[2]), "=r"(d[3]) : "r"(addr));
}

__device__ __forceinline__ void mma_f16(float* c, const uint32_t* a, const uint32_t* b) {
    asm volatile(
        "mma.sync.aligned.m16n8k16.row.col.f32.f16.f16.f32 "
        "{%0,%1,%2,%3}, {%4,%5,%6,%7}, {%8,%9}, {%0,%1,%2,%3};"
        : "+f"(c[0]), "+f"(c[1]), "+f"(c[2]), "+f"(c[3])
        : "r"(a[0]), "r"(a[1]), "r"(a[2]), "r"(a[3]), "r"(b[0]), "r"(b[1]));
}
__device__ __forceinline__ void mma_tf32(float* c, const uint32_t* a, const uint32_t* b) {
    asm volatile(
        "mma.sync.aligned.m16n8k8.row.col.f32.tf32.tf32.f32 "
        "{%0,%1,%2,%3}, {%4,%5,%6,%7}, {%8,%9}, {%0,%1,%2,%3};"
        : "+f"(c[0]), "+f"(c[1]), "+f"(c[2]), "+f"(c[3])
        : "r"(a[0]), "r"(a[1]), "r"(a[2]), "r"(a[3]), "r"(b[0]), "r"(b[1]));
}

// fp16-tile ldmatrix addressing
__device__ __forceinline__ uint32_t addrA(uint32_t sbase, int mrow, int c0) {
    int l = threadIdx.x & 31;
    int r = mrow + (l & 15);
    int c = c0 + (l >> 4);
    return sbase + sw_chunk_off(r, c);
}
__device__ __forceinline__ uint32_t addrB(uint32_t sbase, int nrow, int c0) {
    int l = threadIdx.x & 31;
    int r = nrow + (l & 7) + ((l >> 4) << 3);
    int c = c0 + ((l >> 3) & 1);
    return sbase + sw_chunk_off(r, c);
}
// tf32-tile ldmatrix addressing.
// A m16k8 (cbase = 16B-chunk index of the k8 slice): 4 b16 8x8 mats =
// (r0-7,c),(r8-15,c),(r0-7,c+1),(r8-15,c+1) -> regs land exactly on a0..a3.
__device__ __forceinline__ uint32_t addrA32(uint32_t sbase, int mrow, int cbase) {
    int l = threadIdx.x & 31;
    int r = mrow + (l & 7) + ((l >> 3) & 1) * 8;
    int c = cbase + ((l >> 4) & 1);
    return sbase + sw8_off(r, c);
}
// B n8k16 (cbase = chunk of k16 slice): mats = (n0-7, chunks c..c+3);
// reg0,1 = b0,b1 of k8#0; reg2,3 = b0,b1 of k8#1.
__device__ __forceinline__ uint32_t addrB32(uint32_t sbase, int nrow, int cbase) {
    int l = threadIdx.x & 31;
    int r = nrow + (l & 7);
    int c = cbase + (l >> 3);
    return sbase + sw8_off(r, c);
}

// 16-bit tile loader: ROWS x 32 elems (64B rows) at (row0, kb).
template <int ROWS>
__device__ __forceinline__ void load_tile_async(uint32_t sbase,
                                                const void* __restrict__ g,
                                                int row0, int kb)
{
    int t = threadIdx.x;
    const char* gb = (const char*)g + ((size_t)row0 * 1024 + kb) * 2;
#pragma unroll
    for (int i = 0; i < (ROWS * 4) / 256; i++) {
        int idx = i * 256 + t;
        int r = idx >> 2;
        int c = idx & 3;
        const char* src = gb + (size_t)r * 2048 + c * 16;
        uint32_t dst = sbase + sw_chunk_off(r, c);
        asm volatile("cp.async.cg.shared.global [%0], [%1], 16;"
                     :: "r"(dst), "l"(src) : "memory");
    }
}
// tf32 tile loader: ROWS x 32 floats (128B rows) at (row0, kb).
template <int ROWS>
__device__ __forceinline__ void load_tile32_async(uint32_t sbase,
                                                  const float* __restrict__ g,
                                                  int row0, int kb)
{
    int t = threadIdx.x;
    const char* gb = (const char*)(g + (size_t)row0 * 1024 + kb);
#pragma unroll
    for (int i = 0; i < (ROWS * 8) / 256; i++) {
        int idx = i * 256 + t;
        int r = idx >> 3;
        int c = idx & 7;
        const char* src = gb + (size_t)r * 4096 + c * 16;
        uint32_t dst = sbase + sw8_off(r, c);
        asm volatile("cp.async.cg.shared.global [%0], [%1], 16;"
                     :: "r"(dst), "l"(src) : "memory");
    }
}
#define CP_COMMIT()  asm volatile("cp.async.commit_group;" ::: "memory")
#define CP_WAIT(n)   asm volatile("cp.async.wait_group %0;" :: "n"(n) : "memory")

__device__ __forceinline__ float to_tf32(float v) {
    uint32_t b;
    asm("cvt.rna.tf32.f32 %0, %1;" : "=r"(b) : "f"(v));
    return __uint_as_float(b);
}

// ---------------- prep kernels ---------------------------------------------
__global__ __launch_bounds__(256) void convert_x_kernel(
    const float* __restrict__ src, __half* __restrict__ dst, int n4)
{
    int i = blockIdx.x * 256 + threadIdx.x;
    if (i >= n4) return;
    float4 v = ((const float4*)src)[i];
    __half2* dp = (__half2*)(dst + (size_t)i * 4);
    dp[0] = __halves2half2(__float2half_rn(v.x), __float2half_rn(v.y));
    dp[1] = __halves2half2(__float2half_rn(v.z), __float2half_rn(v.w));
}

__global__ __launch_bounds__(256) void convert_w16_kernel(
    const float* __restrict__ s0, const float* __restrict__ s1,
    const float* __restrict__ s2,
    __half* __restrict__ d0, __half* __restrict__ d1, __half* __restrict__ d2)
{
    const float* s;
    __half* d;
    switch (blockIdx.y) {
        case 0:  s = s0; d = d0; break;
        case 1:  s = s1; d = d1; break;
        default: s = s2; d = d2; break;
    }
    int i = blockIdx.x * 256 + threadIdx.x;
    float4 v = ((const float4*)s)[i];
    __half2* dp = (__half2*)(d + (size_t)i * 4);
    dp[0] = __halves2half2(__float2half_rn(v.x), __float2half_rn(v.y));
    dp[1] = __halves2half2(__float2half_rn(v.z), __float2half_rn(v.w));
}

// Cw -> tf32-rounded fp32
__global__ __launch_bounds__(256) void convert_cwt_kernel(
    const float* __restrict__ src, float* __restrict__ dst)
{
    int i = blockIdx.x * 256 + threadIdx.x;
    float4 v = ((const float4*)src)[i];
    float4 o;
    o.x = to_tf32(v.x); o.y = to_tf32(v.y);
    o.z = to_tf32(v.z); o.w = to_tf32(v.w);
    ((float4*)dst)[i] = o;
}

// ---------------- kernel 1: dual GEMM (x@dw^T, x@Bw^T) + SSM epilogue ------
// fp16 single-term. CTA 128x64; 8 warps 4m x 2n; warp 32x32; BK=32; 3-stage.
// Stage (16KB): xh 0, dw 8192, Bw 12288.
__global__ __launch_bounds__(256, 2)
void gemm1_kernel(const float* __restrict__ dbias, const float* __restrict__ Bb,
                  const float* __restrict__ Avec)
{
    extern __shared__ char smem[];
    uint32_t sb = smem_u32(smem);
    const int t = threadIdx.x, wid = t >> 5, lane = t & 31;
    const int m0 = blockIdx.y * 128, n0 = blockIdx.x * 64;
    const int wm = (wid & 3) * 32;
    const int wn = (wid >> 2) * 32;

    float acc1[2][4][4], acc2[2][4][4];
#pragma unroll
    for (int i = 0; i < 2; i++)
#pragma unroll
        for (int j = 0; j < 4; j++)
#pragma unroll
            for (int q = 0; q < 4; q++) { acc1[i][j][q] = 0.f; acc2[i][j][q] = 0.f; }

    auto issue_stage = [&](int s, int kidx) {
        uint32_t st = sb + s * 16384;
        int kb = kidx * 32;
        load_tile_async<128>(st,          g_xh,  m0, kb);
        load_tile_async<64> (st + 8192,   g_dwh, n0, kb);
        load_tile_async<64> (st + 12288,  g_Bwh, n0, kb);
        CP_COMMIT();
    };
    issue_stage(0, 0);
    issue_stage(1, 1);

    const int K = 32;
    for (int k = 0; k < K; k++) {
        if (k + 2 < K) CP_WAIT(1); else CP_WAIT(0);
        __syncthreads();
        if (k + 2 < K) issue_stage((k + 2) % 3, k + 2);

        uint32_t st = sb + (k % 3) * 16384;
#pragma unroll
        for (int kk = 0; kk < 2; kk++) {
            int c0 = kk * 2;
            uint32_t ah[2][4];
#pragma unroll
            for (int mt = 0; mt < 2; mt++)
                ldsm4(ah[mt], addrA(st, wm + mt * 16, c0));
            uint32_t b1[8], b2[8];
            ldsm4(b1,     addrB(st + 8192,  wn,      c0));
            ldsm4(b1 + 4, addrB(st + 8192,  wn + 16, c0));
            ldsm4(b2,     addrB(st + 12288, wn,      c0));
            ldsm4(b2 + 4, addrB(st + 12288, wn + 16, c0));
#pragma unroll
            for (int mt = 0; mt < 2; mt++)
#pragma unroll
                for (int nt = 0; nt < 4; nt++) {
                    mma_f16(acc1[mt][nt], ah[mt], &b1[nt * 2]);
                    mma_f16(acc2[mt][nt], ah[mt], &b2[nt * 2]);
                }
        }
    }

    // epilogue
    const int lr = lane >> 2, lc = lane & 3;
    float dbv[4][2], avv[4][2], bbv[4][2];
#pragma unroll
    for (int nt = 0; nt < 4; nt++)
#pragma unroll
        for (int j = 0; j < 2; j++) {
            int n = n0 + wn + nt * 8 + lc * 2 + j;
            dbv[nt][j] = __ldg(&dbias[n]);
            avv[nt][j] = __ldg(&Avec[n]);
            bbv[nt][j] = __ldg(&Bb[n]);
        }
#pragma unroll
    for (int mt = 0; mt < 2; mt++)
#pragma unroll
        for (int half = 0; half < 2; half++) {
            int m = m0 + wm + mt * 16 + half * 8 + lr;
            size_t rowo = (size_t)m * DHSZ;
#pragma unroll
            for (int nt = 0; nt < 4; nt++) {
                int n = n0 + wn + nt * 8 + lc * 2;
                float2 oa, ob;
#pragma unroll
                for (int j = 0; j < 2; j++) {
                    float t1 = acc1[mt][nt][half * 2 + j] + dbv[nt][j];
                    float e = __expf(-fabsf(t1));
                    float delta = fmaxf(t1, 0.f) + __logf(1.f + e);
                    float a = __expf(delta * avv[nt][j]);
                    float b = delta * (acc2[mt][nt][half * 2 + j] + bbv[nt][j]);
                    if (j == 0) { oa.x = a; ob.x = b; } else { oa.y = a; ob.y = b; }
                }
                *(float2*)&g_Abar[rowo + n] = oa;
                *(float2*)&g_Bbar[rowo + n] = ob;
            }
        }
}

// ---------------- kernel 2: linear recurrence scan (H -> tf32 fp32) --------
__global__ __launch_bounds__(256) void scan_kernel()
{
    int c = blockIdx.x * 256 + threadIdx.x;   // 0..8191
    int b = c >> 10;
    int h = c & (DHSZ - 1);
    size_t base = (size_t)b * LSZ * DHSZ + h;

    float hp = 0.f;
    for (int l0 = 0; l0 < LSZ; l0 += 16) {
        float av[16], bv[16];
#pragma unroll
        for (int u = 0; u < 16; u++) {
            size_t o = base + (size_t)(l0 + u) * DHSZ;
            av[u] = g_Abar[o];
            bv[u] = g_Bbar[o];
        }
#pragma unroll
        for (int u = 0; u < 16; u++) {
            hp = fmaf(av[u], hp, bv[u]);
            g_H[base + (size_t)(l0 + u) * DHSZ] = to_tf32(hp);
        }
    }
}

// ---------------- kernel 3: out = h@Cw^T (tf32) + x@Dw^T (fp16) ------------
// CTA 128x128; 8 warps 2m x 4n; warp 64x32; BK=32; 3-stage pipe.
// Stage (32KB): pass1: H 0 (16KB), Cwt 16384 (16KB).
//               pass2: xh 0 (8KB),  Dwh 16384 (8KB).
__global__ __launch_bounds__(256, 2)
void gemm3_kernel(const float* __restrict__ Cb, const float* __restrict__ Db,
                  float* __restrict__ out)
{
    extern __shared__ char smem[];
    uint32_t sb = smem_u32(smem);
    const int t = threadIdx.x, wid = t >> 5, lane = t & 31;
    const int m0 = blockIdx.y * 128, n0 = blockIdx.x * 128;
    const int wm = (wid & 1) * 64;
    const int wn = (wid >> 1) * 32;

    float acc[4][4][4];
#pragma unroll
    for (int i = 0; i < 4; i++)
#pragma unroll
        for (int j = 0; j < 4; j++)
#pragma unroll
            for (int q = 0; q < 4; q++) acc[i][j][q] = 0.f;

    auto issue_stage = [&](int s, int kidx) {
        uint32_t st = sb + s * 32768;
        int kb = (kidx & 31) * 32;
        if (kidx < 32) {      // pass 1: h @ Cw^T, tf32 single-term
            load_tile32_async<128>(st,          g_H,   m0, kb);
            load_tile32_async<128>(st + 16384,  g_Cwt, n0, kb);
        } else {              // pass 2: x @ Dw^T, fp16 single-term
            load_tile_async<128>(st,          g_xh,  m0, kb);
            load_tile_async<128>(st + 16384,  g_Dwh, n0, kb);
        }
        CP_COMMIT();
    };
    issue_stage(0, 0);
    issue_stage(1, 1);

    const int K = 64;
    for (int k = 0; k < K; k++) {
        if (k + 2 < K) CP_WAIT(1); else CP_WAIT(0);
        __syncthreads();
        if (k + 2 < K) issue_stage((k + 2) % 3, k + 2);

        uint32_t st = sb + (k % 3) * 32768;
        if (k < 32) {
            // tf32: per k16 half (q): B ldsm covers k16; A per k8.
#pragma unroll
            for (int q = 0; q < 2; q++) {
                uint32_t bb[4][4];
#pragma unroll
                for (int nt = 0; nt < 4; nt++)
                    ldsm4(bb[nt], addrB32(st + 16384, wn + nt * 8, q * 4));
#pragma unroll
                for (int k8 = 0; k8 < 2; k8++) {
                    uint32_t aa[4][4];
#pragma unroll
                    for (int mt = 0; mt < 4; mt++)
                        ldsm4(aa[mt], addrA32(st, wm + mt * 16, q * 4 + k8 * 2));
#pragma unroll
                    for (int mt = 0; mt < 4; mt++)
#pragma unroll
                        for (int nt = 0; nt < 4; nt++)
                            mma_tf32(acc[mt][nt], aa[mt], &bb[nt][k8 * 2]);
                }
            }
        } else {
            // fp16 single-term
#pragma unroll
            for (int kk = 0; kk < 2; kk++) {
                int c0 = kk * 2;
                uint32_t ah[4][4];
#pragma unroll
                for (int mt = 0; mt < 4; mt++)
                    ldsm4(ah[mt], addrA(st, wm + mt * 16, c0));
                uint32_t bh[8];
                ldsm4(bh,     addrB(st + 16384, wn,      c0));
                ldsm4(bh + 4, addrB(st + 16384, wn + 16, c0));
#pragma unroll
                for (int mt = 0; mt < 4; mt++)
#pragma unroll
                    for (int nt = 0; nt < 4; nt++)
                        mma_f16(acc[mt][nt], ah[mt], &bh[nt * 2]);
            }
        }
    }

    const int lr = lane >> 2, lc = lane & 3;
    float biasv[4][2];
#pragma unroll
    for (int nt = 0; nt < 4; nt++)
#pragma unroll
        for (int j = 0; j < 2; j++) {
            int n = n0 + wn + nt * 8 + lc * 2 + j;
            biasv[nt][j] = __ldg(&Cb[n]) + __ldg(&Db[n]);
        }
#pragma unroll
    for (int mt = 0; mt < 4; mt++)
#pragma unroll
        for (int half = 0; half < 2; half++) {
            int m = m0 + wm + mt * 16 + half * 8 + lr;
            size_t rowo = (size_t)m * DMSZ;
#pragma unroll
            for (int nt = 0; nt < 4; nt++) {
                int n = n0 + wn + nt * 8 + lc * 2;
                float2 o;
                o.x = acc[mt][nt][half * 2 + 0] + biasv[nt][0];
                o.y = acc[mt][nt][half * 2 + 1] + biasv[nt][1];
                *(float2*)&out[rowo + n] = o;
            }
        }
}

// ---------------- launch ---------------------------------------------------
// Inputs: 0:x 1:A 2:Bw 3:Bb 4:Cw 5:Cb 6:Dw 7:Db 8:dw 9:db
extern "C" void kernel_launch(void* const* d_in, const int* in_sizes, int n_in,
                              void* d_out, int out_size)
{
    const float* x    = (const float*)d_in[0];
    const float* Avec = (const float*)d_in[1];
    const float* Bw   = (const float*)d_in[2];
    const float* Bb   = (const float*)d_in[3];
    const float* Cw   = (const float*)d_in[4];
    const float* Cb   = (const float*)d_in[5];
    const float* Dw   = (const float*)d_in[6];
    const float* Db   = (const float*)d_in[7];
    const float* dw   = (const float*)d_in[8];
    const float* db   = (const float*)d_in[9];
    float* out = (float*)d_out;

    void *xh, *dwh, *bwh, *Dwh, *cwt;
    cudaGetSymbolAddress(&xh, g_xh);
    cudaGetSymbolAddress(&dwh, g_dwh);   cudaGetSymbolAddress(&bwh, g_Bwh);
    cudaGetSymbolAddress(&Dwh, g_Dwh);   cudaGetSymbolAddress(&cwt, g_Cwt);

    cudaFuncSetAttribute(gemm1_kernel, cudaFuncAttributeMaxDynamicSharedMemorySize, 49152);
    cudaFuncSetAttribute(gemm3_kernel, cudaFuncAttributeMaxDynamicSharedMemorySize, 98304);

    int nx4 = (MSZ * DMSZ) / 4;       // 4,194,304
    int nw4 = (DHSZ * DMSZ) / 4;      // 262,144
    convert_x_kernel<<<nx4 / 256, 256>>>(x, (__half*)xh, nx4);
    dim3 gw(nw4 / 256, 3);
    convert_w16_kernel<<<gw, 256>>>(dw, Bw, Dw, (__half*)dwh, (__half*)bwh, (__half*)Dwh);
    convert_cwt_kernel<<<nw4 / 256, 256>>>(Cw, (float*)cwt);

    dim3 g1(DHSZ / 64, MSZ / 128);    // (16, 128)
    gemm1_kernel<<<g1, 256, 49152>>>(db, Bb, Avec);

    scan_kernel<<<(BSZ * DHSZ) / 256, 256>>>();

    dim3 g3(DMSZ / 128, MSZ / 128);   // (8, 128)
    gemm3_kernel<<<g3, 256, 98304>>>(Cb, Db, out);
}

// round 14
// speedup vs baseline: 2.5572x; 1.2478x over previous
#include <cuda_runtime.h>
#include <cuda_fp16.h>
#include <cstdint>

#define BSZ  8
#define LSZ  2048
#define DMSZ 1024
#define DHSZ 1024
#define MSZ  (BSZ * LSZ)   // 16384

// ---------------- scratch (__device__ globals; allocation-free rule) -------
__device__ __half g_xh[(size_t)MSZ * DMSZ];     // x fp16
__device__ __half g_dwh[DHSZ * DMSZ];
__device__ __half g_Bwh[DHSZ * DMSZ];
__device__ __half g_Dwh[DMSZ * DMSZ];
__device__ __half g_Cwh[DMSZ * DHSZ];
__device__ float  g_H[(size_t)MSZ * DHSZ];      // h fp32 (scan output)
__device__ __half g_Hq[(size_t)MSZ * DHSZ];     // h / s_row, fp16
__device__ float  g_Srow[MSZ];                  // per-row pow2 scale
__device__ float  g_Abar[(size_t)MSZ * DHSZ];
__device__ float  g_Bbar[(size_t)MSZ * DHSZ];

// ---------------- helpers --------------------------------------------------
__device__ __forceinline__ uint32_t smem_u32(const void* p) {
    uint32_t a;
    asm("{ .reg .u64 t; cvta.to.shared.u64 t, %1; cvt.u32.u64 %0, t; }"
        : "=r"(a) : "l"(p));
    return a;
}

// 16-bit tiles: rows of 32 elems = 64B = 4 chunks of 16B; chunk ^= (row>>1)&3.
__device__ __forceinline__ uint32_t sw_chunk_off(int r, int c) {
    return (uint32_t)(((r << 2) | (c ^ ((r >> 1) & 3))) << 4);
}

__device__ __forceinline__ void ldsm4(uint32_t* d, uint32_t addr) {
    asm volatile("ldmatrix.sync.aligned.m8n8.x4.shared.b16 {%0,%1,%2,%3}, [%4];"
                 : "=r"(d[0]), "=r"(d[1]), "=r"(d[2]), "=r"(d[3]) : "r"(addr));
}

__device__ __forceinline__ void mma_f16(float* c, const uint32_t* a, const uint32_t* b) {
    asm volatile(
        "mma.sync.aligned.m16n8k16.row.col.f32.f16.f16.f32 "
        "{%0,%1,%2,%3}, {%4,%5,%6,%7}, {%8,%9}, {%0,%1,%2,%3};"
        : "+f"(c[0]), "+f"(c[1]), "+f"(c[2]), "+f"(c[3])
        : "r"(a[0]), "r"(a[1]), "r"(a[2]), "r"(a[3]), "r"(b[0]), "r"(b[1]));
}

__device__ __forceinline__ uint32_t addrA(uint32_t sbase, int mrow, int c0) {
    int l = threadIdx.x & 31;
    int r = mrow + (l & 15);
    int c = c0 + (l >> 4);
    return sbase + sw_chunk_off(r, c);
}
__device__ __forceinline__ uint32_t addrB(uint32_t sbase, int nrow, int c0) {
    int l = threadIdx.x & 31;
    int r = nrow + (l & 7) + ((l >> 4) << 3);
    int c = c0 + ((l >> 3) & 1);
    return sbase + sw_chunk_off(r, c);
}

// 16-bit tile loader: ROWS x 32 elems (64B rows) at (row0, kb).
template <int ROWS>
__device__ __forceinline__ void load_tile_async(uint32_t sbase,
                                                const void* __restrict__ g,
                                                int row0, int kb)
{
    int t = threadIdx.x;
    const char* gb = (const char*)g + ((size_t)row0 * 1024 + kb) * 2;
#pragma unroll
    for (int i = 0; i < (ROWS * 4) / 256; i++) {
        int idx = i * 256 + t;
        int r = idx >> 2;
        int c = idx & 3;
        const char* src = gb + (size_t)r * 2048 + c * 16;
        uint32_t dst = sbase + sw_chunk_off(r, c);
        asm volatile("cp.async.cg.shared.global [%0], [%1], 16;"
                     :: "r"(dst), "l"(src) : "memory");
    }
}
#define CP_COMMIT()  asm volatile("cp.async.commit_group;" ::: "memory")
#define CP_WAIT(n)   asm volatile("cp.async.wait_group %0;" :: "n"(n) : "memory")

// ---------------- prep kernels ---------------------------------------------
__global__ __launch_bounds__(256) void convert_x_kernel(
    const float* __restrict__ src, __half* __restrict__ dst, int n4)
{
    int i = blockIdx.x * 256 + threadIdx.x;
    if (i >= n4) return;
    float4 v = ((const float4*)src)[i];
    __half2* dp = (__half2*)(dst + (size_t)i * 4);
    dp[0] = __halves2half2(__float2half_rn(v.x), __float2half_rn(v.y));
    dp[1] = __halves2half2(__float2half_rn(v.z), __float2half_rn(v.w));
}

// dw, Bw, Dw, Cw -> single fp16 (blockIdx.y selects)
__global__ __launch_bounds__(256) void convert_w16_kernel(
    const float* __restrict__ s0, const float* __restrict__ s1,
    const float* __restrict__ s2, const float* __restrict__ s3,
    __half* __restrict__ d0, __half* __restrict__ d1,
    __half* __restrict__ d2, __half* __restrict__ d3)
{
    const float* s;
    __half* d;
    switch (blockIdx.y) {
        case 0:  s = s0; d = d0; break;
        case 1:  s = s1; d = d1; break;
        case 2:  s = s2; d = d2; break;
        default: s = s3; d = d3; break;
    }
    int i = blockIdx.x * 256 + threadIdx.x;
    float4 v = ((const float4*)s)[i];
    __half2* dp = (__half2*)(d + (size_t)i * 4);
    dp[0] = __halves2half2(__float2half_rn(v.x), __float2half_rn(v.y));
    dp[1] = __halves2half2(__float2half_rn(v.z), __float2half_rn(v.w));
}

// ---------------- kernel 1: dual GEMM (x@dw^T, x@Bw^T) + SSM epilogue ------
// fp16 single-term. CTA 128x64; 8 warps 4m x 2n; warp 32x32; BK=32; 3-stage.
// Stage (16KB): xh 0, dw 8192, Bw 12288.
__global__ __launch_bounds__(256, 2)
void gemm1_kernel(const float* __restrict__ dbias, const float* __restrict__ Bb,
                  const float* __restrict__ Avec)
{
    extern __shared__ char smem[];
    uint32_t sb = smem_u32(smem);
    const int t = threadIdx.x, wid = t >> 5, lane = t & 31;
    const int m0 = blockIdx.y * 128, n0 = blockIdx.x * 64;
    const int wm = (wid & 3) * 32;
    const int wn = (wid >> 2) * 32;

    float acc1[2][4][4], acc2[2][4][4];
#pragma unroll
    for (int i = 0; i < 2; i++)
#pragma unroll
        for (int j = 0; j < 4; j++)
#pragma unroll
            for (int q = 0; q < 4; q++) { acc1[i][j][q] = 0.f; acc2[i][j][q] = 0.f; }

    auto issue_stage = [&](int s, int kidx) {
        uint32_t st = sb + s * 16384;
        int kb = kidx * 32;
        load_tile_async<128>(st,          g_xh,  m0, kb);
        load_tile_async<64> (st + 8192,   g_dwh, n0, kb);
        load_tile_async<64> (st + 12288,  g_Bwh, n0, kb);
        CP_COMMIT();
    };
    issue_stage(0, 0);
    issue_stage(1, 1);

    const int K = 32;
    for (int k = 0; k < K; k++) {
        if (k + 2 < K) CP_WAIT(1); else CP_WAIT(0);
        __syncthreads();
        if (k + 2 < K) issue_stage((k + 2) % 3, k + 2);

        uint32_t st = sb + (k % 3) * 16384;
#pragma unroll
        for (int kk = 0; kk < 2; kk++) {
            int c0 = kk * 2;
            uint32_t ah[2][4];
#pragma unroll
            for (int mt = 0; mt < 2; mt++)
                ldsm4(ah[mt], addrA(st, wm + mt * 16, c0));
            uint32_t b1[8], b2[8];
            ldsm4(b1,     addrB(st + 8192,  wn,      c0));
            ldsm4(b1 + 4, addrB(st + 8192,  wn + 16, c0));
            ldsm4(b2,     addrB(st + 12288, wn,      c0));
            ldsm4(b2 + 4, addrB(st + 12288, wn + 16, c0));
#pragma unroll
            for (int mt = 0; mt < 2; mt++)
#pragma unroll
                for (int nt = 0; nt < 4; nt++) {
                    mma_f16(acc1[mt][nt], ah[mt], &b1[nt * 2]);
                    mma_f16(acc2[mt][nt], ah[mt], &b2[nt * 2]);
                }
        }
    }

    // epilogue
    const int lr = lane >> 2, lc = lane & 3;
    float dbv[4][2], avv[4][2], bbv[4][2];
#pragma unroll
    for (int nt = 0; nt < 4; nt++)
#pragma unroll
        for (int j = 0; j < 2; j++) {
            int n = n0 + wn + nt * 8 + lc * 2 + j;
            dbv[nt][j] = __ldg(&dbias[n]);
            avv[nt][j] = __ldg(&Avec[n]);
            bbv[nt][j] = __ldg(&Bb[n]);
        }
#pragma unroll
    for (int mt = 0; mt < 2; mt++)
#pragma unroll
        for (int half = 0; half < 2; half++) {
            int m = m0 + wm + mt * 16 + half * 8 + lr;
            size_t rowo = (size_t)m * DHSZ;
#pragma unroll
            for (int nt = 0; nt < 4; nt++) {
                int n = n0 + wn + nt * 8 + lc * 2;
                float2 oa, ob;
#pragma unroll
                for (int j = 0; j < 2; j++) {
                    float t1 = acc1[mt][nt][half * 2 + j] + dbv[nt][j];
                    float e = __expf(-fabsf(t1));
                    float delta = fmaxf(t1, 0.f) + __logf(1.f + e);
                    float a = __expf(delta * avv[nt][j]);
                    float b = delta * (acc2[mt][nt][half * 2 + j] + bbv[nt][j]);
                    if (j == 0) { oa.x = a; ob.x = b; } else { oa.y = a; ob.y = b; }
                }
                *(float2*)&g_Abar[rowo + n] = oa;
                *(float2*)&g_Bbar[rowo + n] = ob;
            }
        }
}

// ---------------- kernel 2: linear recurrence scan (H -> fp32) -------------
__global__ __launch_bounds__(256) void scan_kernel()
{
    int c = blockIdx.x * 256 + threadIdx.x;   // 0..8191
    int b = c >> 10;
    int h = c & (DHSZ - 1);
    size_t base = (size_t)b * LSZ * DHSZ + h;

    float hp = 0.f;
    for (int l0 = 0; l0 < LSZ; l0 += 32) {
        float av[32], bv[32];
#pragma unroll
        for (int u = 0; u < 32; u++) {
            size_t o = base + (size_t)(l0 + u) * DHSZ;
            av[u] = g_Abar[o];
            bv[u] = g_Bbar[o];
        }
#pragma unroll
        for (int u = 0; u < 32; u++) {
            hp = fmaf(av[u], hp, bv[u]);
            g_H[base + (size_t)(l0 + u) * DHSZ] = hp;
        }
    }
}

// ---------------- kernel 2b: per-row pow2 scale + fp16 quantize ------------
// One block (128 threads) per row m: s = next pow2 >= rowmax(|h|);
// Hq = h / s (exact pow2 division), Srow[m] = s.
__global__ __launch_bounds__(128) void rowquant_kernel()
{
    int m = blockIdx.x;
    int t = threadIdx.x;
    const float4* row = (const float4*)(g_H + (size_t)m * DHSZ);
    float4 v0 = row[t];
    float4 v1 = row[t + 128];
    float mx = fmaxf(fmaxf(fabsf(v0.x), fabsf(v0.y)), fmaxf(fabsf(v0.z), fabsf(v0.w)));
    mx = fmaxf(mx, fmaxf(fmaxf(fabsf(v1.x), fabsf(v1.y)), fmaxf(fabsf(v1.z), fabsf(v1.w))));
#pragma unroll
    for (int o = 16; o; o >>= 1)
        mx = fmaxf(mx, __shfl_xor_sync(0xFFFFFFFFu, mx, o));
    __shared__ float wmx[4];
    if ((t & 31) == 0) wmx[t >> 5] = mx;
    __syncthreads();
    mx = fmaxf(fmaxf(wmx[0], wmx[1]), fmaxf(wmx[2], wmx[3]));

    uint32_t bits = __float_as_uint(mx);
    uint32_t e = (bits & 0x7f800000u) + ((bits & 0x007fffffu) ? 0x00800000u : 0u);
    if (mx == 0.f) e = 0x3f800000u;          // s = 1 for all-zero row
    float s = __uint_as_float(e);
    float inv = 1.f / s;                      // exact (pow2)
    if (t == 0) g_Srow[m] = s;

    __half2* dst = (__half2*)(g_Hq + (size_t)m * DHSZ);
    dst[t * 2 + 0]       = __halves2half2(__float2half_rn(v0.x * inv), __float2half_rn(v0.y * inv));
    dst[t * 2 + 1]       = __halves2half2(__float2half_rn(v0.z * inv), __float2half_rn(v0.w * inv));
    dst[(t + 128) * 2]     = __halves2half2(__float2half_rn(v1.x * inv), __float2half_rn(v1.y * inv));
    dst[(t + 128) * 2 + 1] = __halves2half2(__float2half_rn(v1.z * inv), __float2half_rn(v1.w * inv));
}

// ---------------- kernel 3: out = s_m*(Hq@Cw^T) + x@Dw^T + Cb + Db ---------
// All fp16. CTA 128x128; 8 warps 2m x 4n; warp 64x32; BK=32; 3-stage pipe.
// Stage (16KB): A 0, B 8192. Pass1 k<32: (Hq, Cw); pass2: (xh, Dw).
// At k==32 boundary, acc *= Srow (per-row pow2 scale).
__global__ __launch_bounds__(256, 2)
void gemm3_kernel(const float* __restrict__ Cb, const float* __restrict__ Db,
                  float* __restrict__ out)
{
    extern __shared__ char smem[];
    uint32_t sb = smem_u32(smem);
    const int t = threadIdx.x, wid = t >> 5, lane = t & 31;
    const int m0 = blockIdx.y * 128, n0 = blockIdx.x * 128;
    const int wm = (wid & 1) * 64;
    const int wn = (wid >> 1) * 32;
    const int lr = lane >> 2, lc = lane & 3;

    float acc[4][4][4];
#pragma unroll
    for (int i = 0; i < 4; i++)
#pragma unroll
        for (int j = 0; j < 4; j++)
#pragma unroll
            for (int q = 0; q < 4; q++) acc[i][j][q] = 0.f;

    auto issue_stage = [&](int s, int kidx) {
        uint32_t st = sb + s * 16384;
        int kb = (kidx & 31) * 32;
        if (kidx < 32) {
            load_tile_async<128>(st,         g_Hq,  m0, kb);
            load_tile_async<128>(st + 8192,  g_Cwh, n0, kb);
        } else {
            load_tile_async<128>(st,         g_xh,  m0, kb);
            load_tile_async<128>(st + 8192,  g_Dwh, n0, kb);
        }
        CP_COMMIT();
    };
    issue_stage(0, 0);
    issue_stage(1, 1);

    const int K = 64;
    for (int k = 0; k < K; k++) {
        if (k + 2 < K) CP_WAIT(1); else CP_WAIT(0);
        __syncthreads();
        if (k + 2 < K) issue_stage((k + 2) % 3, k + 2);

        if (k == 32) {
            // scale pass-1 accumulators by per-row pow2 s_m
#pragma unroll
            for (int mt = 0; mt < 4; mt++)
#pragma unroll
                for (int half = 0; half < 2; half++) {
                    float s = __ldg(&g_Srow[m0 + wm + mt * 16 + half * 8 + lr]);
#pragma unroll
                    for (int nt = 0; nt < 4; nt++) {
                        acc[mt][nt][half * 2 + 0] *= s;
                        acc[mt][nt][half * 2 + 1] *= s;
                    }
                }
        }

        uint32_t st = sb + (k % 3) * 16384;
#pragma unroll
        for (int kk = 0; kk < 2; kk++) {
            int c0 = kk * 2;
            uint32_t ah[4][4];
#pragma unroll
            for (int mt = 0; mt < 4; mt++)
                ldsm4(ah[mt], addrA(st, wm + mt * 16, c0));
            uint32_t bh[8];
            ldsm4(bh,     addrB(st + 8192, wn,      c0));
            ldsm4(bh + 4, addrB(st + 8192, wn + 16, c0));
#pragma unroll
            for (int mt = 0; mt < 4; mt++)
#pragma unroll
                for (int nt = 0; nt < 4; nt++)
                    mma_f16(acc[mt][nt], ah[mt], &bh[nt * 2]);
        }
    }

    float biasv[4][2];
#pragma unroll
    for (int nt = 0; nt < 4; nt++)
#pragma unroll
        for (int j = 0; j < 2; j++) {
            int n = n0 + wn + nt * 8 + lc * 2 + j;
            biasv[nt][j] = __ldg(&Cb[n]) + __ldg(&Db[n]);
        }
#pragma unroll
    for (int mt = 0; mt < 4; mt++)
#pragma unroll
        for (int half = 0; half < 2; half++) {
            int m = m0 + wm + mt * 16 + half * 8 + lr;
            size_t rowo = (size_t)m * DMSZ;
#pragma unroll
            for (int nt = 0; nt < 4; nt++) {
                int n = n0 + wn + nt * 8 + lc * 2;
                float2 o;
                o.x = acc[mt][nt][half * 2 + 0] + biasv[nt][0];
                o.y = acc[mt][nt][half * 2 + 1] + biasv[nt][1];
                *(float2*)&out[rowo + n] = o;
            }
        }
}

// ---------------- launch ---------------------------------------------------
// Inputs: 0:x 1:A 2:Bw 3:Bb 4:Cw 5:Cb 6:Dw 7:Db 8:dw 9:db
extern "C" void kernel_launch(void* const* d_in, const int* in_sizes, int n_in,
                              void* d_out, int out_size)
{
    const float* x    = (const float*)d_in[0];
    const float* Avec = (const float*)d_in[1];
    const float* Bw   = (const float*)d_in[2];
    const float* Bb   = (const float*)d_in[3];
    const float* Cw   = (const float*)d_in[4];
    const float* Cb   = (const float*)d_in[5];
    const float* Dw   = (const float*)d_in[6];
    const float* Db   = (const float*)d_in[7];
    const float* dw   = (const float*)d_in[8];
    const float* db   = (const float*)d_in[9];
    float* out = (float*)d_out;

    void *xh, *dwh, *bwh, *Dwh, *cwh;
    cudaGetSymbolAddress(&xh, g_xh);
    cudaGetSymbolAddress(&dwh, g_dwh);   cudaGetSymbolAddress(&bwh, g_Bwh);
    cudaGetSymbolAddress(&Dwh, g_Dwh);   cudaGetSymbolAddress(&cwh, g_Cwh);

    cudaFuncSetAttribute(gemm1_kernel, cudaFuncAttributeMaxDynamicSharedMemorySize, 49152);
    cudaFuncSetAttribute(gemm3_kernel, cudaFuncAttributeMaxDynamicSharedMemorySize, 49152);

    int nx4 = (MSZ * DMSZ) / 4;       // 4,194,304
    int nw4 = (DHSZ * DMSZ) / 4;      // 262,144
    convert_x_kernel<<<nx4 / 256, 256>>>(x, (__half*)xh, nx4);
    dim3 gw(nw4 / 256, 4);
    convert_w16_kernel<<<gw, 256>>>(dw, Bw, Dw, Cw,
                                    (__half*)dwh, (__half*)bwh, (__half*)Dwh, (__half*)cwh);

    dim3 g1(DHSZ / 64, MSZ / 128);    // (16, 128)
    gemm1_kernel<<<g1, 256, 49152>>>(db, Bb, Avec);

    scan_kernel<<<(BSZ * DHSZ) / 256, 256>>>();

    rowquant_kernel<<<MSZ, 128>>>();

    dim3 g3(DMSZ / 128, MSZ / 128);   // (8, 128)
    gemm3_kernel<<<g3, 256, 49152>>>(Cb, Db, out);
}

// round 15
// speedup vs baseline: 2.5805x; 1.0091x over previous
#include <cuda_runtime.h>
#include <cuda_fp16.h>
#include <cstdint>

#define BSZ  8
#define LSZ  2048
#define DMSZ 1024
#define DHSZ 1024
#define MSZ  (BSZ * LSZ)   // 16384

// ---------------- scratch (__device__ globals; allocation-free rule) -------
__device__ __half g_xh[(size_t)MSZ * DMSZ];     // x fp16
__device__ __half g_dwh[DHSZ * DMSZ];
__device__ __half g_Bwh[DHSZ * DMSZ];
__device__ __half g_Dwh[DMSZ * DMSZ];
__device__ __half g_Cwh[DMSZ * DHSZ];
__device__ float  g_H[(size_t)MSZ * DHSZ];      // h fp32 (scan output)
__device__ __half g_Hq[(size_t)MSZ * DHSZ];     // h / s_row, fp16
__device__ float  g_Srow[MSZ];                  // per-row pow2 scale
__device__ float  g_Abar[(size_t)MSZ * DHSZ];
__device__ float  g_Bbar[(size_t)MSZ * DHSZ];

// ---------------- helpers --------------------------------------------------
__device__ __forceinline__ uint32_t smem_u32(const void* p) {
    uint32_t a;
    asm("{ .reg .u64 t; cvta.to.shared.u64 t, %1; cvt.u32.u64 %0, t; }"
        : "=r"(a) : "l"(p));
    return a;
}

// 16-bit tiles: rows of 32 elems = 64B = 4 chunks of 16B; chunk ^= (row>>1)&3.
__device__ __forceinline__ uint32_t sw_chunk_off(int r, int c) {
    return (uint32_t)(((r << 2) | (c ^ ((r >> 1) & 3))) << 4);
}

__device__ __forceinline__ void ldsm4(uint32_t* d, uint32_t addr) {
    asm volatile("ldmatrix.sync.aligned.m8n8.x4.shared.b16 {%0,%1,%2,%3}, [%4];"
                 : "=r"(d[0]), "=r"(d[1]), "=r"(d[2]), "=r"(d[3]) : "r"(addr));
}

__device__ __forceinline__ void mma_f16(float* c, const uint32_t* a, const uint32_t* b) {
    asm volatile(
        "mma.sync.aligned.m16n8k16.row.col.f32.f16.f16.f32 "
        "{%0,%1,%2,%3}, {%4,%5,%6,%7}, {%8,%9}, {%0,%1,%2,%3};"
        : "+f"(c[0]), "+f"(c[1]), "+f"(c[2]), "+f"(c[3])
        : "r"(a[0]), "r"(a[1]), "r"(a[2]), "r"(a[3]), "r"(b[0]), "r"(b[1]));
}

__device__ __forceinline__ uint32_t addrA(uint32_t sbase, int mrow, int c0) {
    int l = threadIdx.x & 31;
    int r = mrow + (l & 15);
    int c = c0 + (l >> 4);
    return sbase + sw_chunk_off(r, c);
}
__device__ __forceinline__ uint32_t addrB(uint32_t sbase, int nrow, int c0) {
    int l = threadIdx.x & 31;
    int r = nrow + (l & 7) + ((l >> 4) << 3);
    int c = c0 + ((l >> 3) & 1);
    return sbase + sw_chunk_off(r, c);
}

// 16-bit tile loader: ROWS x 32 elems (64B rows) at (row0, kb).
template <int ROWS>
__device__ __forceinline__ void load_tile_async(uint32_t sbase,
                                                const void* __restrict__ g,
                                                int row0, int kb)
{
    int t = threadIdx.x;
    const char* gb = (const char*)g + ((size_t)row0 * 1024 + kb) * 2;
#pragma unroll
    for (int i = 0; i < (ROWS * 4) / 256; i++) {
        int idx = i * 256 + t;
        int r = idx >> 2;
        int c = idx & 3;
        const char* src = gb + (size_t)r * 2048 + c * 16;
        uint32_t dst = sbase + sw_chunk_off(r, c);
        asm volatile("cp.async.cg.shared.global [%0], [%1], 16;"
                     :: "r"(dst), "l"(src) : "memory");
    }
}
#define CP_COMMIT()  asm volatile("cp.async.commit_group;" ::: "memory")
#define CP_WAIT(n)   asm volatile("cp.async.wait_group %0;" :: "n"(n) : "memory")

// ---------------- prep kernels ---------------------------------------------
__global__ __launch_bounds__(256) void convert_x_kernel(
    const float* __restrict__ src, __half* __restrict__ dst, int n4)
{
    int i = blockIdx.x * 256 + threadIdx.x;
    if (i >= n4) return;
    float4 v = ((const float4*)src)[i];
    __half2* dp = (__half2*)(dst + (size_t)i * 4);
    dp[0] = __halves2half2(__float2half_rn(v.x), __float2half_rn(v.y));
    dp[1] = __halves2half2(__float2half_rn(v.z), __float2half_rn(v.w));
}

// dw, Bw, Dw, Cw -> single fp16 (blockIdx.y selects)
__global__ __launch_bounds__(256) void convert_w16_kernel(
    const float* __restrict__ s0, const float* __restrict__ s1,
    const float* __restrict__ s2, const float* __restrict__ s3,
    __half* __restrict__ d0, __half* __restrict__ d1,
    __half* __restrict__ d2, __half* __restrict__ d3)
{
    const float* s;
    __half* d;
    switch (blockIdx.y) {
        case 0:  s = s0; d = d0; break;
        case 1:  s = s1; d = d1; break;
        case 2:  s = s2; d = d2; break;
        default: s = s3; d = d3; break;
    }
    int i = blockIdx.x * 256 + threadIdx.x;
    float4 v = ((const float4*)s)[i];
    __half2* dp = (__half2*)(d + (size_t)i * 4);
    dp[0] = __halves2half2(__float2half_rn(v.x), __float2half_rn(v.y));
    dp[1] = __halves2half2(__float2half_rn(v.z), __float2half_rn(v.w));
}

// ---------------- kernel 1: dual GEMM (x@dw^T, x@Bw^T) + SSM epilogue ------
// fp16 single-term. CTA 128x64; 8 warps 4m x 2n; warp 32x32; BK=32; 4-stage.
// Stage (16KB): xh 0, dw 8192, Bw 12288.
__global__ __launch_bounds__(256, 2)
void gemm1_kernel(const float* __restrict__ dbias, const float* __restrict__ Bb,
                  const float* __restrict__ Avec)
{
    extern __shared__ char smem[];
    uint32_t sb = smem_u32(smem);
    const int t = threadIdx.x, wid = t >> 5, lane = t & 31;
    const int m0 = blockIdx.y * 128, n0 = blockIdx.x * 64;
    const int wm = (wid & 3) * 32;
    const int wn = (wid >> 2) * 32;

    float acc1[2][4][4], acc2[2][4][4];
#pragma unroll
    for (int i = 0; i < 2; i++)
#pragma unroll
        for (int j = 0; j < 4; j++)
#pragma unroll
            for (int q = 0; q < 4; q++) { acc1[i][j][q] = 0.f; acc2[i][j][q] = 0.f; }

    auto issue_stage = [&](int s, int kidx) {
        uint32_t st = sb + s * 16384;
        int kb = kidx * 32;
        load_tile_async<128>(st,          g_xh,  m0, kb);
        load_tile_async<64> (st + 8192,   g_dwh, n0, kb);
        load_tile_async<64> (st + 12288,  g_Bwh, n0, kb);
        CP_COMMIT();
    };
    issue_stage(0, 0);
    issue_stage(1, 1);
    issue_stage(2, 2);

    const int K = 32;
    for (int k = 0; k < K; k++) {
        if (k < K - 2)       CP_WAIT(2);
        else if (k == K - 2) CP_WAIT(1);
        else                 CP_WAIT(0);
        __syncthreads();
        if (k + 3 < K) issue_stage((k + 3) & 3, k + 3);

        uint32_t st = sb + (k & 3) * 16384;
#pragma unroll
        for (int kk = 0; kk < 2; kk++) {
            int c0 = kk * 2;
            uint32_t ah[2][4];
#pragma unroll
            for (int mt = 0; mt < 2; mt++)
                ldsm4(ah[mt], addrA(st, wm + mt * 16, c0));
            uint32_t b1[8], b2[8];
            ldsm4(b1,     addrB(st + 8192,  wn,      c0));
            ldsm4(b1 + 4, addrB(st + 8192,  wn + 16, c0));
            ldsm4(b2,     addrB(st + 12288, wn,      c0));
            ldsm4(b2 + 4, addrB(st + 12288, wn + 16, c0));
#pragma unroll
            for (int mt = 0; mt < 2; mt++)
#pragma unroll
                for (int nt = 0; nt < 4; nt++) {
                    mma_f16(acc1[mt][nt], ah[mt], &b1[nt * 2]);
                    mma_f16(acc2[mt][nt], ah[mt], &b2[nt * 2]);
                }
        }
    }

    // epilogue
    const int lr = lane >> 2, lc = lane & 3;
    float dbv[4][2], avv[4][2], bbv[4][2];
#pragma unroll
    for (int nt = 0; nt < 4; nt++)
#pragma unroll
        for (int j = 0; j < 2; j++) {
            int n = n0 + wn + nt * 8 + lc * 2 + j;
            dbv[nt][j] = __ldg(&dbias[n]);
            avv[nt][j] = __ldg(&Avec[n]);
            bbv[nt][j] = __ldg(&Bb[n]);
        }
#pragma unroll
    for (int mt = 0; mt < 2; mt++)
#pragma unroll
        for (int half = 0; half < 2; half++) {
            int m = m0 + wm + mt * 16 + half * 8 + lr;
            size_t rowo = (size_t)m * DHSZ;
#pragma unroll
            for (int nt = 0; nt < 4; nt++) {
                int n = n0 + wn + nt * 8 + lc * 2;
                float2 oa, ob;
#pragma unroll
                for (int j = 0; j < 2; j++) {
                    float t1 = acc1[mt][nt][half * 2 + j] + dbv[nt][j];
                    float e = __expf(-fabsf(t1));
                    float delta = fmaxf(t1, 0.f) + __logf(1.f + e);
                    float a = __expf(delta * avv[nt][j]);
                    float b = delta * (acc2[mt][nt][half * 2 + j] + bbv[nt][j]);
                    if (j == 0) { oa.x = a; ob.x = b; } else { oa.y = a; ob.y = b; }
                }
                *(float2*)&g_Abar[rowo + n] = oa;
                *(float2*)&g_Bbar[rowo + n] = ob;
            }
        }
}

// ---------------- kernel 2: linear recurrence scan (H -> fp32) -------------
// 32-thread CTAs, 256 CTAs: spread the 8192 channels across all SMs.
__global__ __launch_bounds__(32) void scan_kernel()
{
    int c = blockIdx.x * 32 + threadIdx.x;    // 0..8191
    int b = c >> 10;
    int h = c & (DHSZ - 1);
    size_t base = (size_t)b * LSZ * DHSZ + h;

    float hp = 0.f;
    for (int l0 = 0; l0 < LSZ; l0 += 32) {
        float av[32], bv[32];
#pragma unroll
        for (int u = 0; u < 32; u++) {
            size_t o = base + (size_t)(l0 + u) * DHSZ;
            av[u] = g_Abar[o];
            bv[u] = g_Bbar[o];
        }
#pragma unroll
        for (int u = 0; u < 32; u++) {
            hp = fmaf(av[u], hp, bv[u]);
            g_H[base + (size_t)(l0 + u) * DHSZ] = hp;
        }
    }
}

// ---------------- kernel 2b: per-row pow2 scale + fp16 quantize ------------
// One block (128 threads) per row m: s = next pow2 >= rowmax(|h|);
// Hq = h / s (exact pow2 division), Srow[m] = s.
__global__ __launch_bounds__(128) void rowquant_kernel()
{
    int m = blockIdx.x;
    int t = threadIdx.x;
    const float4* row = (const float4*)(g_H + (size_t)m * DHSZ);
    float4 v0 = row[t];
    float4 v1 = row[t + 128];
    float mx = fmaxf(fmaxf(fabsf(v0.x), fabsf(v0.y)), fmaxf(fabsf(v0.z), fabsf(v0.w)));
    mx = fmaxf(mx, fmaxf(fmaxf(fabsf(v1.x), fabsf(v1.y)), fmaxf(fabsf(v1.z), fabsf(v1.w))));
#pragma unroll
    for (int o = 16; o; o >>= 1)
        mx = fmaxf(mx, __shfl_xor_sync(0xFFFFFFFFu, mx, o));
    __shared__ float wmx[4];
    if ((t & 31) == 0) wmx[t >> 5] = mx;
    __syncthreads();
    mx = fmaxf(fmaxf(wmx[0], wmx[1]), fmaxf(wmx[2], wmx[3]));

    uint32_t bits = __float_as_uint(mx);
    uint32_t e = (bits & 0x7f800000u) + ((bits & 0x007fffffu) ? 0x00800000u : 0u);
    if (mx == 0.f) e = 0x3f800000u;          // s = 1 for all-zero row
    float s = __uint_as_float(e);
    float inv = 1.f / s;                      // exact (pow2)
    if (t == 0) g_Srow[m] = s;

    __half2* dst = (__half2*)(g_Hq + (size_t)m * DHSZ);
    dst[t * 2 + 0]       = __halves2half2(__float2half_rn(v0.x * inv), __float2half_rn(v0.y * inv));
    dst[t * 2 + 1]       = __halves2half2(__float2half_rn(v0.z * inv), __float2half_rn(v0.w * inv));
    dst[(t + 128) * 2]     = __halves2half2(__float2half_rn(v1.x * inv), __float2half_rn(v1.y * inv));
    dst[(t + 128) * 2 + 1] = __halves2half2(__float2half_rn(v1.z * inv), __float2half_rn(v1.w * inv));
}

// ---------------- kernel 3: out = s_m*(Hq@Cw^T) + x@Dw^T + Cb + Db ---------
// All fp16. CTA 128x128; 8 warps 2m x 4n; warp 64x32; BK=32; 4-stage pipe.
// Stage (16KB): A 0, B 8192. Pass1 k<32: (Hq, Cw); pass2: (xh, Dw).
// At k==32 boundary, acc *= Srow (per-row pow2 scale).
__global__ __launch_bounds__(256, 2)
void gemm3_kernel(const float* __restrict__ Cb, const float* __restrict__ Db,
                  float* __restrict__ out)
{
    extern __shared__ char smem[];
    uint32_t sb = smem_u32(smem);
    const int t = threadIdx.x, wid = t >> 5, lane = t & 31;
    const int m0 = blockIdx.y * 128, n0 = blockIdx.x * 128;
    const int wm = (wid & 1) * 64;
    const int wn = (wid >> 1) * 32;
    const int lr = lane >> 2, lc = lane & 3;

    float acc[4][4][4];
#pragma unroll
    for (int i = 0; i < 4; i++)
#pragma unroll
        for (int j = 0; j < 4; j++)
#pragma unroll
            for (int q = 0; q < 4; q++) acc[i][j][q] = 0.f;

    auto issue_stage = [&](int s, int kidx) {
        uint32_t st = sb + s * 16384;
        int kb = (kidx & 31) * 32;
        if (kidx < 32) {
            load_tile_async<128>(st,         g_Hq,  m0, kb);
            load_tile_async<128>(st + 8192,  g_Cwh, n0, kb);
        } else {
            load_tile_async<128>(st,         g_xh,  m0, kb);
            load_tile_async<128>(st + 8192,  g_Dwh, n0, kb);
        }
        CP_COMMIT();
    };
    issue_stage(0, 0);
    issue_stage(1, 1);
    issue_stage(2, 2);

    const int K = 64;
    for (int k = 0; k < K; k++) {
        if (k < K - 2)       CP_WAIT(2);
        else if (k == K - 2) CP_WAIT(1);
        else                 CP_WAIT(0);
        __syncthreads();
        if (k + 3 < K) issue_stage((k + 3) & 3, k + 3);

        if (k == 32) {
            // scale pass-1 accumulators by per-row pow2 s_m
#pragma unroll
            for (int mt = 0; mt < 4; mt++)
#pragma unroll
                for (int half = 0; half < 2; half++) {
                    float s = __ldg(&g_Srow[m0 + wm + mt * 16 + half * 8 + lr]);
#pragma unroll
                    for (int nt = 0; nt < 4; nt++) {
                        acc[mt][nt][half * 2 + 0] *= s;
                        acc[mt][nt][half * 2 + 1] *= s;
                    }
                }
        }

        uint32_t st = sb + (k & 3) * 16384;
#pragma unroll
        for (int kk = 0; kk < 2; kk++) {
            int c0 = kk * 2;
            uint32_t ah[4][4];
#pragma unroll
            for (int mt = 0; mt < 4; mt++)
                ldsm4(ah[mt], addrA(st, wm + mt * 16, c0));
            uint32_t bh[8];
            ldsm4(bh,     addrB(st + 8192, wn,      c0));
            ldsm4(bh + 4, addrB(st + 8192, wn + 16, c0));
#pragma unroll
            for (int mt = 0; mt < 4; mt++)
#pragma unroll
                for (int nt = 0; nt < 4; nt++)
                    mma_f16(acc[mt][nt], ah[mt], &bh[nt * 2]);
        }
    }

    float biasv[4][2];
#pragma unroll
    for (int nt = 0; nt < 4; nt++)
#pragma unroll
        for (int j = 0; j < 2; j++) {
            int n = n0 + wn + nt * 8 + lc * 2 + j;
            biasv[nt][j] = __ldg(&Cb[n]) + __ldg(&Db[n]);
        }
#pragma unroll
    for (int mt = 0; mt < 4; mt++)
#pragma unroll
        for (int half = 0; half < 2; half++) {
            int m = m0 + wm + mt * 16 + half * 8 + lr;
            size_t rowo = (size_t)m * DMSZ;
#pragma unroll
            for (int nt = 0; nt < 4; nt++) {
                int n = n0 + wn + nt * 8 + lc * 2;
                float2 o;
                o.x = acc[mt][nt][half * 2 + 0] + biasv[nt][0];
                o.y = acc[mt][nt][half * 2 + 1] + biasv[nt][1];
                *(float2*)&out[rowo + n] = o;
            }
        }
}

// ---------------- launch ---------------------------------------------------
// Inputs: 0:x 1:A 2:Bw 3:Bb 4:Cw 5:Cb 6:Dw 7:Db 8:dw 9:db
extern "C" void kernel_launch(void* const* d_in, const int* in_sizes, int n_in,
                              void* d_out, int out_size)
{
    const float* x    = (const float*)d_in[0];
    const float* Avec = (const float*)d_in[1];
    const float* Bw   = (const float*)d_in[2];
    const float* Bb   = (const float*)d_in[3];
    const float* Cw   = (const float*)d_in[4];
    const float* Cb   = (const float*)d_in[5];
    const float* Dw   = (const float*)d_in[6];
    const float* Db   = (const float*)d_in[7];
    const float* dw   = (const float*)d_in[8];
    const float* db   = (const float*)d_in[9];
    float* out = (float*)d_out;

    void *xh, *dwh, *bwh, *Dwh, *cwh;
    cudaGetSymbolAddress(&xh, g_xh);
    cudaGetSymbolAddress(&dwh, g_dwh);   cudaGetSymbolAddress(&bwh, g_Bwh);
    cudaGetSymbolAddress(&Dwh, g_Dwh);   cudaGetSymbolAddress(&cwh, g_Cwh);

    cudaFuncSetAttribute(gemm1_kernel, cudaFuncAttributeMaxDynamicSharedMemorySize, 65536);
    cudaFuncSetAttribute(gemm3_kernel, cudaFuncAttributeMaxDynamicSharedMemorySize, 65536);

    int nx4 = (MSZ * DMSZ) / 4;       // 4,194,304
    int nw4 = (DHSZ * DMSZ) / 4;      // 262,144
    convert_x_kernel<<<nx4 / 256, 256>>>(x, (__half*)xh, nx4);
    dim3 gw(nw4 / 256, 4);
    convert_w16_kernel<<<gw, 256>>>(dw, Bw, Dw, Cw,
                                    (__half*)dwh, (__half*)bwh, (__half*)Dwh, (__half*)cwh);

    dim3 g1(DHSZ / 64, MSZ / 128);    // (16, 128)
    gemm1_kernel<<<g1, 256, 65536>>>(db, Bb, Avec);

    scan_kernel<<<(BSZ * DHSZ) / 32, 32>>>();

    rowquant_kernel<<<MSZ, 128>>>();

    dim3 g3(DMSZ / 128, MSZ / 128);   // (8, 128)
    gemm3_kernel<<<g3, 256, 65536>>>(Cb, Db, out);
}

// round 16
// speedup vs baseline: 2.7837x; 1.0787x over previous
#include <cuda_runtime.h>
#include <cuda_fp16.h>
#include <cstdint>

#define BSZ  8
#define LSZ  2048
#define DMSZ 1024
#define DHSZ 1024
#define MSZ  (BSZ * LSZ)   // 16384
#define NCH  16            // scan chunks
#define CHL  (LSZ / NCH)   // 128 steps per chunk
#define NCHN (BSZ * DHSZ)  // 8192 channels

// ---------------- scratch (__device__ globals; allocation-free rule) -------
__device__ __half g_xh[(size_t)MSZ * DMSZ];     // x fp16
__device__ __half g_dwh[DHSZ * DMSZ];
__device__ __half g_Bwh[DHSZ * DMSZ];
__device__ __half g_Dwh[DMSZ * DMSZ];
__device__ __half g_Cwh[DMSZ * DHSZ];
__device__ float  g_H[(size_t)MSZ * DHSZ];      // h fp32 (scan output)
__device__ __half g_Hq[(size_t)MSZ * DHSZ];     // h / s_row, fp16
__device__ float  g_Srow[MSZ];                  // per-row pow2 scale
__device__ float  g_Abar[(size_t)MSZ * DHSZ];
__device__ float  g_Bbar[(size_t)MSZ * DHSZ];
__device__ float  g_pA[NCH * NCHN];             // chunk summaries
__device__ float  g_pB[NCH * NCHN];
__device__ float  g_h0[NCH * NCHN];             // chunk-start states

// ---------------- helpers --------------------------------------------------
__device__ __forceinline__ uint32_t smem_u32(const void* p) {
    uint32_t a;
    asm("{ .reg .u64 t; cvta.to.shared.u64 t, %1; cvt.u32.u64 %0, t; }"
        : "=r"(a) : "l"(p));
    return a;
}

// 16-bit tiles: rows of 32 elems = 64B = 4 chunks of 16B; chunk ^= (row>>1)&3.
__device__ __forceinline__ uint32_t sw_chunk_off(int r, int c) {
    return (uint32_t)(((r << 2) | (c ^ ((r >> 1) & 3))) << 4);
}

__device__ __forceinline__ void ldsm4(uint32_t* d, uint32_t addr) {
    asm volatile("ldmatrix.sync.aligned.m8n8.x4.shared.b16 {%0,%1,%2,%3}, [%4];"
                 : "=r"(d[0]), "=r"(d[1]), "=r"(d[2]), "=r"(d[3]) : "r"(addr));
}

__device__ __forceinline__ void mma_f16(float* c, const uint32_t* a, const uint32_t* b) {
    asm volatile(
        "mma.sync.aligned.m16n8k16.row.col.f32.f16.f16.f32 "
        "{%0,%1,%2,%3}, {%4,%5,%6,%7}, {%8,%9}, {%0,%1,%2,%3};"
        : "+f"(c[0]), "+f"(c[1]), "+f"(c[2]), "+f"(c[3])
        : "r"(a[0]), "r"(a[1]), "r"(a[2]), "r"(a[3]), "r"(b[0]), "r"(b[1]));
}

__device__ __forceinline__ uint32_t addrA(uint32_t sbase, int mrow, int c0) {
    int l = threadIdx.x & 31;
    int r = mrow + (l & 15);
    int c = c0 + (l >> 4);
    return sbase + sw_chunk_off(r, c);
}
__device__ __forceinline__ uint32_t addrB(uint32_t sbase, int nrow, int c0) {
    int l = threadIdx.x & 31;
    int r = nrow + (l & 7) + ((l >> 4) << 3);
    int c = c0 + ((l >> 3) & 1);
    return sbase + sw_chunk_off(r, c);
}

// 16-bit tile loader: ROWS x 32 elems (64B rows) at (row0, kb).
template <int ROWS>
__device__ __forceinline__ void load_tile_async(uint32_t sbase,
                                                const void* __restrict__ g,
                                                int row0, int kb)
{
    int t = threadIdx.x;
    const char* gb = (const char*)g + ((size_t)row0 * 1024 + kb) * 2;
#pragma unroll
    for (int i = 0; i < (ROWS * 4) / 256; i++) {
        int idx = i * 256 + t;
        int r = idx >> 2;
        int c = idx & 3;
        const char* src = gb + (size_t)r * 2048 + c * 16;
        uint32_t dst = sbase + sw_chunk_off(r, c);
        asm volatile("cp.async.cg.shared.global [%0], [%1], 16;"
                     :: "r"(dst), "l"(src) : "memory");
    }
}
#define CP_COMMIT()  asm volatile("cp.async.commit_group;" ::: "memory")
#define CP_WAIT(n)   asm volatile("cp.async.wait_group %0;" :: "n"(n) : "memory")

// ---------------- prep kernels ---------------------------------------------
__global__ __launch_bounds__(256) void convert_x_kernel(
    const float* __restrict__ src, __half* __restrict__ dst, int n4)
{
    int i = blockIdx.x * 256 + threadIdx.x;
    if (i >= n4) return;
    float4 v = ((const float4*)src)[i];
    __half2* dp = (__half2*)(dst + (size_t)i * 4);
    dp[0] = __halves2half2(__float2half_rn(v.x), __float2half_rn(v.y));
    dp[1] = __halves2half2(__float2half_rn(v.z), __float2half_rn(v.w));
}

// dw, Bw, Dw, Cw -> single fp16 (blockIdx.y selects)
__global__ __launch_bounds__(256) void convert_w16_kernel(
    const float* __restrict__ s0, const float* __restrict__ s1,
    const float* __restrict__ s2, const float* __restrict__ s3,
    __half* __restrict__ d0, __half* __restrict__ d1,
    __half* __restrict__ d2, __half* __restrict__ d3)
{
    const float* s;
    __half* d;
    switch (blockIdx.y) {
        case 0:  s = s0; d = d0; break;
        case 1:  s = s1; d = d1; break;
        case 2:  s = s2; d = d2; break;
        default: s = s3; d = d3; break;
    }
    int i = blockIdx.x * 256 + threadIdx.x;
    float4 v = ((const float4*)s)[i];
    __half2* dp = (__half2*)(d + (size_t)i * 4);
    dp[0] = __halves2half2(__float2half_rn(v.x), __float2half_rn(v.y));
    dp[1] = __halves2half2(__float2half_rn(v.z), __float2half_rn(v.w));
}

// ---------------- kernel 1: dual GEMM (x@dw^T, x@Bw^T) + SSM epilogue ------
// fp16 single-term. CTA 128x64; 8 warps 4m x 2n; warp 32x32; BK=32; 4-stage.
// Stage (16KB): xh 0, dw 8192, Bw 12288.
__global__ __launch_bounds__(256, 2)
void gemm1_kernel(const float* __restrict__ dbias, const float* __restrict__ Bb,
                  const float* __restrict__ Avec)
{
    extern __shared__ char smem[];
    uint32_t sb = smem_u32(smem);
    const int t = threadIdx.x, wid = t >> 5, lane = t & 31;
    const int m0 = blockIdx.y * 128, n0 = blockIdx.x * 64;
    const int wm = (wid & 3) * 32;
    const int wn = (wid >> 2) * 32;

    float acc1[2][4][4], acc2[2][4][4];
#pragma unroll
    for (int i = 0; i < 2; i++)
#pragma unroll
        for (int j = 0; j < 4; j++)
#pragma unroll
            for (int q = 0; q < 4; q++) { acc1[i][j][q] = 0.f; acc2[i][j][q] = 0.f; }

    auto issue_stage = [&](int s, int kidx) {
        uint32_t st = sb + s * 16384;
        int kb = kidx * 32;
        load_tile_async<128>(st,          g_xh,  m0, kb);
        load_tile_async<64> (st + 8192,   g_dwh, n0, kb);
        load_tile_async<64> (st + 12288,  g_Bwh, n0, kb);
        CP_COMMIT();
    };
    issue_stage(0, 0);
    issue_stage(1, 1);
    issue_stage(2, 2);

    const int K = 32;
    for (int k = 0; k < K; k++) {
        if (k < K - 2)       CP_WAIT(2);
        else if (k == K - 2) CP_WAIT(1);
        else                 CP_WAIT(0);
        __syncthreads();
        if (k + 3 < K) issue_stage((k + 3) & 3, k + 3);

        uint32_t st = sb + (k & 3) * 16384;
#pragma unroll
        for (int kk = 0; kk < 2; kk++) {
            int c0 = kk * 2;
            uint32_t ah[2][4];
#pragma unroll
            for (int mt = 0; mt < 2; mt++)
                ldsm4(ah[mt], addrA(st, wm + mt * 16, c0));
            uint32_t b1[8], b2[8];
            ldsm4(b1,     addrB(st + 8192,  wn,      c0));
            ldsm4(b1 + 4, addrB(st + 8192,  wn + 16, c0));
            ldsm4(b2,     addrB(st + 12288, wn,      c0));
            ldsm4(b2 + 4, addrB(st + 12288, wn + 16, c0));
#pragma unroll
            for (int mt = 0; mt < 2; mt++)
#pragma unroll
                for (int nt = 0; nt < 4; nt++) {
                    mma_f16(acc1[mt][nt], ah[mt], &b1[nt * 2]);
                    mma_f16(acc2[mt][nt], ah[mt], &b2[nt * 2]);
                }
        }
    }

    // epilogue
    const int lr = lane >> 2, lc = lane & 3;
    float dbv[4][2], avv[4][2], bbv[4][2];
#pragma unroll
    for (int nt = 0; nt < 4; nt++)
#pragma unroll
        for (int j = 0; j < 2; j++) {
            int n = n0 + wn + nt * 8 + lc * 2 + j;
            dbv[nt][j] = __ldg(&dbias[n]);
            avv[nt][j] = __ldg(&Avec[n]);
            bbv[nt][j] = __ldg(&Bb[n]);
        }
#pragma unroll
    for (int mt = 0; mt < 2; mt++)
#pragma unroll
        for (int half = 0; half < 2; half++) {
            int m = m0 + wm + mt * 16 + half * 8 + lr;
            size_t rowo = (size_t)m * DHSZ;
#pragma unroll
            for (int nt = 0; nt < 4; nt++) {
                int n = n0 + wn + nt * 8 + lc * 2;
                float2 oa, ob;
#pragma unroll
                for (int j = 0; j < 2; j++) {
                    float t1 = acc1[mt][nt][half * 2 + j] + dbv[nt][j];
                    float e = __expf(-fabsf(t1));
                    float delta = fmaxf(t1, 0.f) + __logf(1.f + e);
                    float a = __expf(delta * avv[nt][j]);
                    float b = delta * (acc2[mt][nt][half * 2 + j] + bbv[nt][j]);
                    if (j == 0) { oa.x = a; ob.x = b; } else { oa.y = a; ob.y = b; }
                }
                *(float2*)&g_Abar[rowo + n] = oa;
                *(float2*)&g_Bbar[rowo + n] = ob;
            }
        }
}

// ---------------- scan phase A: per-(channel, chunk) summaries -------------
// Thread (c, ch): over 128 steps compute prodA = prod(a), partB = scan(b|h0=0).
// grid (NCHN/256, NCH), block 256. Coalesced along c.
__global__ __launch_bounds__(256) void scanA_kernel()
{
    int c  = blockIdx.x * 256 + threadIdx.x;   // 0..8191
    int ch = blockIdx.y;                        // 0..NCH-1
    int b = c >> 10;
    int h = c & (DHSZ - 1);
    size_t base = (size_t)b * LSZ * DHSZ + (size_t)ch * CHL * DHSZ + h;

    float pa = 1.f, hb = 0.f;
    for (int l0 = 0; l0 < CHL; l0 += 16) {
        float av[16], bv[16];
#pragma unroll
        for (int u = 0; u < 16; u++) {
            size_t o = base + (size_t)(l0 + u) * DHSZ;
            av[u] = g_Abar[o];
            bv[u] = g_Bbar[o];
        }
#pragma unroll
        for (int u = 0; u < 16; u++) {
            hb = fmaf(av[u], hb, bv[u]);
            pa *= av[u];
        }
    }
    g_pA[ch * NCHN + c] = pa;
    g_pB[ch * NCHN + c] = hb;
}

// ---------------- scan phase B: compose summaries -> chunk-start states ----
__global__ __launch_bounds__(256) void scanB_kernel()
{
    int c = blockIdx.x * 256 + threadIdx.x;    // 0..8191
    float h0 = 0.f;
#pragma unroll
    for (int ch = 0; ch < NCH; ch++) {
        g_h0[ch * NCHN + c] = h0;
        h0 = fmaf(g_pA[ch * NCHN + c], h0, g_pB[ch * NCHN + c]);
    }
}

// ---------------- scan phase C: apply + write H ----------------------------
__global__ __launch_bounds__(256) void scanC_kernel()
{
    int c  = blockIdx.x * 256 + threadIdx.x;
    int ch = blockIdx.y;
    int b = c >> 10;
    int h = c & (DHSZ - 1);
    size_t base = (size_t)b * LSZ * DHSZ + (size_t)ch * CHL * DHSZ + h;

    float hp = g_h0[ch * NCHN + c];
    for (int l0 = 0; l0 < CHL; l0 += 16) {
        float av[16], bv[16];
#pragma unroll
        for (int u = 0; u < 16; u++) {
            size_t o = base + (size_t)(l0 + u) * DHSZ;
            av[u] = g_Abar[o];
            bv[u] = g_Bbar[o];
        }
#pragma unroll
        for (int u = 0; u < 16; u++) {
            hp = fmaf(av[u], hp, bv[u]);
            g_H[base + (size_t)(l0 + u) * DHSZ] = hp;
        }
    }
}

// ---------------- kernel 2b: per-row pow2 scale + fp16 quantize ------------
__global__ __launch_bounds__(128) void rowquant_kernel()
{
    int m = blockIdx.x;
    int t = threadIdx.x;
    const float4* row = (const float4*)(g_H + (size_t)m * DHSZ);
    float4 v0 = row[t];
    float4 v1 = row[t + 128];
    float mx = fmaxf(fmaxf(fabsf(v0.x), fabsf(v0.y)), fmaxf(fabsf(v0.z), fabsf(v0.w)));
    mx = fmaxf(mx, fmaxf(fmaxf(fabsf(v1.x), fabsf(v1.y)), fmaxf(fabsf(v1.z), fabsf(v1.w))));
#pragma unroll
    for (int o = 16; o; o >>= 1)
        mx = fmaxf(mx, __shfl_xor_sync(0xFFFFFFFFu, mx, o));
    __shared__ float wmx[4];
    if ((t & 31) == 0) wmx[t >> 5] = mx;
    __syncthreads();
    mx = fmaxf(fmaxf(wmx[0], wmx[1]), fmaxf(wmx[2], wmx[3]));

    uint32_t bits = __float_as_uint(mx);
    uint32_t e = (bits & 0x7f800000u) + ((bits & 0x007fffffu) ? 0x00800000u : 0u);
    if (mx == 0.f) e = 0x3f800000u;          // s = 1 for all-zero row
    float s = __uint_as_float(e);
    float inv = 1.f / s;                      // exact (pow2)
    if (t == 0) g_Srow[m] = s;

    __half2* dst = (__half2*)(g_Hq + (size_t)m * DHSZ);
    dst[t * 2 + 0]       = __halves2half2(__float2half_rn(v0.x * inv), __float2half_rn(v0.y * inv));
    dst[t * 2 + 1]       = __halves2half2(__float2half_rn(v0.z * inv), __float2half_rn(v0.w * inv));
    dst[(t + 128) * 2]     = __halves2half2(__float2half_rn(v1.x * inv), __float2half_rn(v1.y * inv));
    dst[(t + 128) * 2 + 1] = __halves2half2(__float2half_rn(v1.z * inv), __float2half_rn(v1.w * inv));
}

// ---------------- kernel 3: out = s_m*(Hq@Cw^T) + x@Dw^T + Cb + Db ---------
// All fp16. CTA 128x128; 8 warps 2m x 4n; warp 64x32; BK=32; 4-stage pipe.
// Stage (16KB): A 0, B 8192. Pass1 k<32: (Hq, Cw); pass2: (xh, Dw).
// At k==32 boundary, acc *= Srow (per-row pow2 scale).
__global__ __launch_bounds__(256, 2)
void gemm3_kernel(const float* __restrict__ Cb, const float* __restrict__ Db,
                  float* __restrict__ out)
{
    extern __shared__ char smem[];
    uint32_t sb = smem_u32(smem);
    const int t = threadIdx.x, wid = t >> 5, lane = t & 31;
    const int m0 = blockIdx.y * 128, n0 = blockIdx.x * 128;
    const int wm = (wid & 1) * 64;
    const int wn = (wid >> 1) * 32;
    const int lr = lane >> 2, lc = lane & 3;

    float acc[4][4][4];
#pragma unroll
    for (int i = 0; i < 4; i++)
#pragma unroll
        for (int j = 0; j < 4; j++)
#pragma unroll
            for (int q = 0; q < 4; q++) acc[i][j][q] = 0.f;

    auto issue_stage = [&](int s, int kidx) {
        uint32_t st = sb + s * 16384;
        int kb = (kidx & 31) * 32;
        if (kidx < 32) {
            load_tile_async<128>(st,         g_Hq,  m0, kb);
            load_tile_async<128>(st + 8192,  g_Cwh, n0, kb);
        } else {
            load_tile_async<128>(st,         g_xh,  m0, kb);
            load_tile_async<128>(st + 8192,  g_Dwh, n0, kb);
        }
        CP_COMMIT();
    };
    issue_stage(0, 0);
    issue_stage(1, 1);
    issue_stage(2, 2);

    const int K = 64;
    for (int k = 0; k < K; k++) {
        if (k < K - 2)       CP_WAIT(2);
        else if (k == K - 2) CP_WAIT(1);
        else                 CP_WAIT(0);
        __syncthreads();
        if (k + 3 < K) issue_stage((k + 3) & 3, k + 3);

        if (k == 32) {
            // scale pass-1 accumulators by per-row pow2 s_m
#pragma unroll
            for (int mt = 0; mt < 4; mt++)
#pragma unroll
                for (int half = 0; half < 2; half++) {
                    float s = __ldg(&g_Srow[m0 + wm + mt * 16 + half * 8 + lr]);
#pragma unroll
                    for (int nt = 0; nt < 4; nt++) {
                        acc[mt][nt][half * 2 + 0] *= s;
                        acc[mt][nt][half * 2 + 1] *= s;
                    }
                }
        }

        uint32_t st = sb + (k & 3) * 16384;
#pragma unroll
        for (int kk = 0; kk < 2; kk++) {
            int c0 = kk * 2;
            uint32_t ah[4][4];
#pragma unroll
            for (int mt = 0; mt < 4; mt++)
                ldsm4(ah[mt], addrA(st, wm + mt * 16, c0));
            uint32_t bh[8];
            ldsm4(bh,     addrB(st + 8192, wn,      c0));
            ldsm4(bh + 4, addrB(st + 8192, wn + 16, c0));
#pragma unroll
            for (int mt = 0; mt < 4; mt++)
#pragma unroll
                for (int nt = 0; nt < 4; nt++)
                    mma_f16(acc[mt][nt], ah[mt], &bh[nt * 2]);
        }
    }

    float biasv[4][2];
#pragma unroll
    for (int nt = 0; nt < 4; nt++)
#pragma unroll
        for (int j = 0; j < 2; j++) {
            int n = n0 + wn + nt * 8 + lc * 2 + j;
            biasv[nt][j] = __ldg(&Cb[n]) + __ldg(&Db[n]);
        }
#pragma unroll
    for (int mt = 0; mt < 4; mt++)
#pragma unroll
        for (int half = 0; half < 2; half++) {
            int m = m0 + wm + mt * 16 + half * 8 + lr;
            size_t rowo = (size_t)m * DMSZ;
#pragma unroll
            for (int nt = 0; nt < 4; nt++) {
                int n = n0 + wn + nt * 8 + lc * 2;
                float2 o;
                o.x = acc[mt][nt][half * 2 + 0] + biasv[nt][0];
                o.y = acc[mt][nt][half * 2 + 1] + biasv[nt][1];
                *(float2*)&out[rowo + n] = o;
            }
        }
}

// ---------------- launch ---------------------------------------------------
// Inputs: 0:x 1:A 2:Bw 3:Bb 4:Cw 5:Cb 6:Dw 7:Db 8:dw 9:db
extern "C" void kernel_launch(void* const* d_in, const int* in_sizes, int n_in,
                              void* d_out, int out_size)
{
    const float* x    = (const float*)d_in[0];
    const float* Avec = (const float*)d_in[1];
    const float* Bw   = (const float*)d_in[2];
    const float* Bb   = (const float*)d_in[3];
    const float* Cw   = (const float*)d_in[4];
    const float* Cb   = (const float*)d_in[5];
    const float* Dw   = (const float*)d_in[6];
    const float* Db   = (const float*)d_in[7];
    const float* dw   = (const float*)d_in[8];
    const float* db   = (const float*)d_in[9];
    float* out = (float*)d_out;

    void *xh, *dwh, *bwh, *Dwh, *cwh;
    cudaGetSymbolAddress(&xh, g_xh);
    cudaGetSymbolAddress(&dwh, g_dwh);   cudaGetSymbolAddress(&bwh, g_Bwh);
    cudaGetSymbolAddress(&Dwh, g_Dwh);   cudaGetSymbolAddress(&cwh, g_Cwh);

    cudaFuncSetAttribute(gemm1_kernel, cudaFuncAttributeMaxDynamicSharedMemorySize, 65536);
    cudaFuncSetAttribute(gemm3_kernel, cudaFuncAttributeMaxDynamicSharedMemorySize, 65536);

    int nx4 = (MSZ * DMSZ) / 4;       // 4,194,304
    int nw4 = (DHSZ * DMSZ) / 4;      // 262,144
    convert_x_kernel<<<nx4 / 256, 256>>>(x, (__half*)xh, nx4);
    dim3 gw(nw4 / 256, 4);
    convert_w16_kernel<<<gw, 256>>>(dw, Bw, Dw, Cw,
                                    (__half*)dwh, (__half*)bwh, (__half*)Dwh, (__half*)cwh);

    dim3 g1(DHSZ / 64, MSZ / 128);    // (16, 128)
    gemm1_kernel<<<g1, 256, 65536>>>(db, Bb, Avec);

    dim3 gs(NCHN / 256, NCH);         // (32, 16)
    scanA_kernel<<<gs, 256>>>();
    scanB_kernel<<<NCHN / 256, 256>>>();
    scanC_kernel<<<gs, 256>>>();

    rowquant_kernel<<<MSZ, 128>>>();

    dim3 g3(DMSZ / 128, MSZ / 128);   // (8, 128)
    gemm3_kernel<<<g3, 256, 65536>>>(Cb, Db, out);
}